// round 15
// baseline (speedup 1.0000x reference)
#include <cuda_runtime.h>
#include <cuda_bf16.h>
#include <math.h>

#define NROWS 2048
#define EMBED 4096
#define SPLITS 16

typedef unsigned long long ull;

__device__ __forceinline__ void ffma2(ull& d, ull a, ull b) {
    asm("fma.rn.f32x2 %0, %1, %2, %3;" : "=l"(d) : "l"(a), "l"(b), "l"(d));
}
__device__ __forceinline__ ull pack2f(float x, float y) {
    ull r; asm("mov.b64 %0, {%1, %2};" : "=l"(r) : "f"(x), "f"(y)); return r;
}
__device__ __forceinline__ float2 unpack2f(ull v) {
    float2 f; asm("mov.b64 {%0, %1}, %2;" : "=f"(f.x), "=f"(f.y) : "l"(v)); return f;
}
__device__ __forceinline__ int ld_acq(const int* p) {
    int v; asm volatile("ld.acquire.gpu.global.b32 %0, [%1];" : "=r"(v) : "l"(p)); return v;
}
__device__ __forceinline__ void st_rel(int* p, int v) {
    asm volatile("st.release.gpu.global.b32 [%0], %1;" :: "l"(p), "r"(v));
}

// ---------------- scratch ----------------
__device__ float g_part[SPLITS * NROWS * 64];
__device__ float g_XP[NROWS * 256];
__device__ float g_states[NROWS * 192];
__device__ float g_G[EMBED * 32];
__device__ float g_cvec[EMBED];
__device__ float g_b1c[256];
__device__ float g_b2c[128];
__device__ ull g_w1hP[32 * 256];
__device__ ull g_w2P[48 * 128];
__device__ ull g_wc1P[64 * 256];
__device__ float g_wc2Pf[96 * 128];
// flags
__device__ int g_prog[8];
__device__ int g_done90[16];
__device__ int g_doneRX[128];
__device__ int g_done32[16];
__device__ int g_doneRG[128];
__device__ int g_next;

__device__ __forceinline__ float sig_f(float x) {
    return __fdividef(1.0f, 1.0f + __expf(-x));
}
__device__ __forceinline__ float tanh_f(float x) {
    return __fdividef(2.0f, 1.0f + __expf(-2.0f * x)) - 1.0f;
}

// ---------------- merged SPP + prep ----------------
__global__ void spp_prep(const float* __restrict__ frames, float* __restrict__ pooled,
                         const float* __restrict__ spp_w, const float* __restrict__ spp_b,
                         const float* __restrict__ fw, const float* __restrict__ fb,
                         const float* __restrict__ b1i, const float* __restrict__ b1h,
                         const float* __restrict__ w1i, const float* __restrict__ w1h,
                         const float* __restrict__ w2i, const float* __restrict__ w2h,
                         const float* __restrict__ b2i, const float* __restrict__ b2h) {
    const int tid = threadIdx.x;
    if (blockIdx.x < 6144) {
        __shared__ float tmax[144];
        const int nc = blockIdx.x;
        const int n = nc / 3, c = nc % 3;
        const float* img = frames + (size_t)nc * 9216;
        if (tid < 144) {
            const int ti = tid / 12, tj = tid % 12;
            const float* p = img + ti * 8 * 96 + tj * 8;
            float m = -3.402823466e38f;
#pragma unroll
            for (int r = 0; r < 8; r++) {
                float4 v0 = *(const float4*)(p + r * 96);
                float4 v1 = *(const float4*)(p + r * 96 + 4);
                m = fmaxf(m, fmaxf(fmaxf(v0.x, v0.y), fmaxf(v0.z, v0.w)));
                m = fmaxf(m, fmaxf(fmaxf(v1.x, v1.y), fmaxf(v1.z, v1.w)));
            }
            tmax[tid] = m;
        }
        __syncthreads();
        float* orow = pooled + (size_t)n * 90;
        if (tid < 16) {
            int i = tid / 4, j = tid % 4;
            float m = -3.402823466e38f;
            for (int a = 0; a < 3; a++) for (int b = 0; b < 3; b++)
                m = fmaxf(m, tmax[(i * 3 + a) * 12 + (j * 3 + b)]);
            orow[c * 16 + i * 4 + j] = m;
        } else if (tid < 25) {
            int q = tid - 16, i = q / 3, j = q % 3;
            float m = -3.402823466e38f;
            for (int a = 0; a < 4; a++) for (int b = 0; b < 4; b++)
                m = fmaxf(m, tmax[(i * 4 + a) * 12 + (j * 4 + b)]);
            orow[48 + c * 9 + i * 3 + j] = m;
        } else if (tid < 29) {
            int q = tid - 25, i = q / 2, j = q % 2;
            float m = -3.402823466e38f;
            for (int a = 0; a < 6; a++) for (int b = 0; b < 6; b++)
                m = fmaxf(m, tmax[(i * 6 + a) * 12 + (j * 6 + b)]);
            orow[75 + c * 4 + i * 2 + j] = m;
        } else if (tid == 29) {
            float m = -3.402823466e38f;
            for (int a = 0; a < 144; a++) m = fmaxf(m, tmax[a]);
            orow[87 + c] = m;
        }
        return;
    }
    const int blk = blockIdx.x - 6144;
    if (blk < 512) {
        int o = blk * 256 + tid;
        int i = o >> 5, j = o & 31;
        float s = 0.f;
        for (int p = 0; p < 90; p++) s += spp_w[i * 90 + p] * fw[p * 32 + j];
        g_G[o] = s;
    } else if (blk < 528) {
        int i = (blk - 512) * 256 + tid;
        float s = spp_b[i];
        for (int p = 0; p < 90; p++) s += spp_w[i * 90 + p] * fb[p];
        g_cvec[i] = s;
    } else if (blk == 528) {
        g_b1c[tid] = b1i[tid] + b1h[tid];
        if (tid < 128) g_b2c[tid] = b2i[tid] + b2h[tid];
        if (tid < 8) g_prog[tid] = 0;
        if (tid < 16) { g_done90[tid] = 0; g_done32[tid] = 0; }
        if (tid < 128) { g_doneRX[tid] = 0; g_doneRG[tid] = 0; }
        if (tid == 0) g_next = 0;
    } else if (blk == 529) {
        for (int idx = tid; idx < 8192; idx += 256) {
            int k = idx >> 8, r = idx & 255;
            g_w1hP[idx] = pack2f(w1h[r * 64 + 2 * k], w1h[r * 64 + 2 * k + 1]);
        }
    } else if (blk == 530) {
        for (int idx = tid; idx < 6144; idx += 256) {
            int k = idx >> 7, r = idx & 127;
            ull v;
            if (k < 32) v = pack2f(w2i[r * 64 + 2 * k], w2i[r * 64 + 2 * k + 1]);
            else { int k2 = k - 32; v = pack2f(w2h[r * 32 + 2 * k2], w2h[r * 32 + 2 * k2 + 1]); }
            g_w2P[idx] = v;
        }
    } else if (blk == 531) {
        for (int idx = tid; idx < 16384; idx += 256) {
            int k = idx >> 8, r = idx & 255;
            ull v;
            if (k < 32) v = pack2f(w1i[r * 64 + 2 * k], w1i[r * 64 + 2 * k + 1]);
            else { int k2 = k - 32; v = pack2f(w1h[r * 64 + 2 * k2], w1h[r * 64 + 2 * k2 + 1]); }
            g_wc1P[idx] = v;
        }
    } else if (blk == 532) {
        for (int idx = tid; idx < 12288; idx += 256) {
            int k = idx >> 7, g = idx & 127;
            g_wc2Pf[idx] = (k < 64) ? w2i[g * 64 + k] : w2h[g * 32 + (k - 64)];
        }
    }
}

// ---------------- role bodies ----------------
template<int KA, int KAP>
__device__ __forceinline__ void mlp_body(
        float* sm, int tid, int tile, int s,
        const float* __restrict__ Asrc, int lda, int aoff, bool ldcgA,
        const float* __restrict__ W1, const float* __restrict__ b1,
        const float* __restrict__ fc7) {
    constexpr int WS = KAP;
    constexpr int NW = (32 * KA + 255) / 256;
    float* A2 = sm;
    float* W2 = A2 + 128 * KAP;
    float* F2 = W2 + 32 * WS;
    float* Es = F2 + 64 * 36;
    const int m0 = tile * 128;
    for (int idx = tid; idx < 128 * KA; idx += 384) {
        int rr = idx / KA, p = idx - rr * KA;
        const float* src = &Asrc[(size_t)(m0 + rr) * lda + aoff + p];
        A2[rr * KAP + p] = ldcgA ? __ldcg(src) : *src;
    }
    ull acc2[8][4];
#pragma unroll
    for (int i = 0; i < 8; i++)
#pragma unroll
        for (int j = 0; j < 4; j++) acc2[i][j] = 0ull;
    const int kbase = s * 256;
    const int txE = tid & 7, tyE = tid >> 3;
    const int txM = tid & 15, tyM = tid >> 4;
    const int eswM = 4 * (tyM & 7);
    const int fswM = 4 * (txM & 7);
    float pw[NW], pf[8];
    if (tid < 256) {
#pragma unroll
        for (int i = 0; i < NW; i++) {
            int idx = tid + i * 256;
            if (idx < 32 * KA) pw[i] = W1[(size_t)(kbase + idx / KA) * KA + idx % KA];
        }
#pragma unroll
        for (int i = 0; i < 8; i++) {
            int idx = tid + i * 256;
            pf[i] = fc7[(size_t)(idx >> 5) * 4096 + kbase + (idx & 31)];
        }
    }
    for (int kc = 0; kc < 256; kc += 32) {
        const int cg0 = kbase + kc;
        __syncthreads();
        if (tid < 256) {
#pragma unroll
            for (int i = 0; i < NW; i++) {
                int idx = tid + i * 256;
                if (idx < 32 * KA) W2[(idx / KA) * WS + idx % KA] = pw[i];
            }
#pragma unroll
            for (int i = 0; i < 8; i++) {
                int idx = tid + i * 256;
                int n = idx >> 5, kk = idx & 31;
                F2[n * 36 + (kk ^ (4 * ((n >> 2) & 7)))] = pf[i];
            }
        }
        __syncthreads();
        if (tid < 256) {
            if (kc + 32 < 256) {
                const int ng0 = cg0 + 32;
#pragma unroll
                for (int i = 0; i < NW; i++) {
                    int idx = tid + i * 256;
                    if (idx < 32 * KA) pw[i] = W1[(size_t)(ng0 + idx / KA) * KA + idx % KA];
                }
#pragma unroll
                for (int i = 0; i < 8; i++) {
                    int idx = tid + i * 256;
                    pf[i] = fc7[(size_t)(idx >> 5) * 4096 + ng0 + (idx & 31)];
                }
            }
            ull e2[4][4];
#pragma unroll
            for (int i = 0; i < 4; i++)
#pragma unroll
                for (int j = 0; j < 4; j++) e2[i][j] = 0ull;
#pragma unroll 15
            for (int p = 0; p < KA; p += 2) {
                ull a0 = *(const ull*)&A2[(tyE * 4 + 0) * KAP + p];
                ull a1 = *(const ull*)&A2[(tyE * 4 + 1) * KAP + p];
                ull a2 = *(const ull*)&A2[(tyE * 4 + 2) * KAP + p];
                ull a3 = *(const ull*)&A2[(tyE * 4 + 3) * KAP + p];
                ull w0 = *(const ull*)&W2[(txE * 4 + 0) * WS + p];
                ull w1 = *(const ull*)&W2[(txE * 4 + 1) * WS + p];
                ull w2 = *(const ull*)&W2[(txE * 4 + 2) * WS + p];
                ull w3 = *(const ull*)&W2[(txE * 4 + 3) * WS + p];
                ffma2(e2[0][0], a0, w0); ffma2(e2[0][1], a0, w1);
                ffma2(e2[0][2], a0, w2); ffma2(e2[0][3], a0, w3);
                ffma2(e2[1][0], a1, w0); ffma2(e2[1][1], a1, w1);
                ffma2(e2[1][2], a1, w2); ffma2(e2[1][3], a1, w3);
                ffma2(e2[2][0], a2, w0); ffma2(e2[2][1], a2, w1);
                ffma2(e2[2][2], a2, w2); ffma2(e2[2][3], a2, w3);
                ffma2(e2[3][0], a3, w0); ffma2(e2[3][1], a3, w1);
                ffma2(e2[3][2], a3, w2); ffma2(e2[3][3], a3, w3);
            }
#pragma unroll
            for (int i = 0; i < 4; i++) {
                int rr = tyE * 4 + i;
                int swz = 4 * ((rr >> 3) & 7);
#pragma unroll
                for (int j = 0; j < 4; j++) {
                    int c = txE * 4 + j;
                    float2 f = unpack2f(e2[i][j]);
                    float v = f.x + f.y + b1[cg0 + c];
                    Es[rr * 40 + (c ^ swz)] = fmaxf(v, 0.f);
                }
            }
        }
        __syncthreads();
        if (tid < 256) {
#pragma unroll
            for (int kk = 0; kk < 32; kk += 2) {
                ull e[8], fv[4];
#pragma unroll
                for (int i = 0; i < 8; i++)
                    e[i] = *(const ull*)&Es[(tyM * 8 + i) * 40 + (kk ^ eswM)];
#pragma unroll
                for (int j = 0; j < 4; j++)
                    fv[j] = *(const ull*)&F2[(txM * 4 + j) * 36 + (kk ^ fswM)];
#pragma unroll
                for (int i = 0; i < 8; i++)
#pragma unroll
                    for (int j = 0; j < 4; j++) ffma2(acc2[i][j], e[i], fv[j]);
            }
        }
    }
    if (tid < 256) {
#pragma unroll
        for (int i = 0; i < 8; i++)
#pragma unroll
            for (int j = 0; j < 4; j++) {
                float2 f = unpack2f(acc2[i][j]);
                g_part[((size_t)s * NROWS + m0 + tyM * 8 + i) * 64 + txM * 4 + j] = f.x + f.y;
            }
    }
    __threadfence();
    __syncthreads();
}

// ================= MEGA: 148 blocks, work-stealing queue =================
__global__ void __launch_bounds__(384, 1) mega(
        const float* __restrict__ pooled,
        const float* __restrict__ spp_w, const float* __restrict__ spp_b,
        const float* __restrict__ fc7, const float* __restrict__ fc7_b,
        const float* __restrict__ fc8w, const float* __restrict__ fc8b,
        const float* __restrict__ fw, const float* __restrict__ fb,
        float* __restrict__ out, float* __restrict__ fpooled) {
    extern __shared__ float sm[];
    const int blk = blockIdx.x;
    const int tid = threadIdx.x;

    if (blk < 8) {
        // ---------------- scan role on exclusive SM ----------------
        __shared__ __align__(16) float h1s[2][64];
        __shared__ __align__(16) float h2s[2][32];
        const int wid = tid >> 5, lane = tid & 31;
        const int b = blk;
        const float* xp = g_XP + (size_t)b * 65536;
        float* st = g_states + (size_t)b * 49152;
        ull wreg[48];
        float bc2 = 0.f, cst = 0.f;
        const int q = lane & 3;
        int j, r;
        if (wid < 8) {
            j = (wid << 3) + (lane >> 2);
            r = (q << 6) + j;
#pragma unroll
            for (int k = 0; k < 32; k++) wreg[k] = g_w1hP[k * 256 + r];
        } else {
            j = ((wid - 8) << 3) + (lane >> 2);
            r = (q << 5) + j;
#pragma unroll
            for (int k = 0; k < 48; k++) wreg[k] = g_w2P[k * 128 + r];
            bc2 = g_b2c[r];
        }
        if (tid < 64) { h1s[0][tid] = 0.f; h1s[1][tid] = 0.f; }
        if (tid >= 64 && tid < 96) { h2s[0][tid - 64] = 0.f; h2s[1][tid - 64] = 0.f; }
        while (ld_acq(&g_doneRX[16 * b]) < 1) __nanosleep(256);
        float xcur = 0.f, x1 = 0.f;
        if (wid < 8) { xcur = __ldcg(&xp[r]); x1 = __ldcg(&xp[256 + r]); }
        __syncthreads();
        for (int t = 0; t <= 256; t++) {
            if ((t & 31) == 0 && t) {
                __threadfence();
                __syncthreads();
                if (tid == 0) st_rel(&g_prog[b], t - 1);
            }
            const int buf = t & 1;
            if (wid < 8) {
                if (t < 256) {
                    float x2 = 0.f;
                    const int row2 = t + 2;
                    if (row2 < 256) {
                        if ((row2 & 15) == 0) {
                            while (ld_acq(&g_doneRX[16 * b + (row2 >> 4)]) < 1) __nanosleep(128);
                        }
                        x2 = __ldcg(&xp[row2 * 256 + r]);
                    }
                    const float* hb = h1s[buf];
                    ull a0 = pack2f(xcur, 0.f), a1 = 0ull, a2 = 0ull, a3 = 0ull;
#pragma unroll
                    for (int k = 0; k < 8; k++) {
                        ulonglong2 hA = *(const ulonglong2*)&hb[8 * k + 0];
                        ulonglong2 hB = *(const ulonglong2*)&hb[8 * k + 4];
                        ffma2(a0, wreg[4 * k + 0], hA.x);
                        ffma2(a1, wreg[4 * k + 1], hA.y);
                        ffma2(a2, wreg[4 * k + 2], hB.x);
                        ffma2(a3, wreg[4 * k + 3], hB.y);
                    }
                    float2 f0 = unpack2f(a0), f1 = unpack2f(a1);
                    float2 f2 = unpack2f(a2), f3 = unpack2f(a3);
                    float g = ((f0.x + f0.y) + (f1.x + f1.y)) + ((f2.x + f2.y) + (f3.x + f3.y));
                    float act = (q == 2) ? tanh_f(g) : sig_f(g);
                    const int base = lane & ~3;
                    float fi = __shfl_sync(0xffffffffu, act, base + 0);
                    float ff = __shfl_sync(0xffffffffu, act, base + 1);
                    float fg = __shfl_sync(0xffffffffu, act, base + 2);
                    float fo = __shfl_sync(0xffffffffu, act, base + 3);
                    if (q == 0) {
                        float c = ff * cst + fi * fg;
                        float h = fo * tanh_f(c);
                        cst = c;
                        h1s[buf ^ 1][j] = h;
                        st[t * 192 + j] = h;
                        st[t * 192 + 64 + j] = c;
                    }
                    xcur = x1; x1 = x2;
                }
            } else if (t >= 1) {
                const int tp = t - 1;
                const float* hb1 = h1s[buf];
                const float* hb2 = h2s[buf];
                ull a0 = pack2f(bc2, 0.f), a1 = 0ull, a2 = 0ull, a3 = 0ull;
#pragma unroll
                for (int k = 0; k < 8; k++) {
                    ulonglong2 hA = *(const ulonglong2*)&hb1[8 * k + 0];
                    ulonglong2 hB = *(const ulonglong2*)&hb1[8 * k + 4];
                    ffma2(a0, wreg[4 * k + 0], hA.x);
                    ffma2(a1, wreg[4 * k + 1], hA.y);
                    ffma2(a2, wreg[4 * k + 2], hB.x);
                    ffma2(a3, wreg[4 * k + 3], hB.y);
                }
#pragma unroll
                for (int k = 0; k < 4; k++) {
                    ulonglong2 hA = *(const ulonglong2*)&hb2[8 * k + 0];
                    ulonglong2 hB = *(const ulonglong2*)&hb2[8 * k + 4];
                    ffma2(a0, wreg[32 + 4 * k + 0], hA.x);
                    ffma2(a1, wreg[32 + 4 * k + 1], hA.y);
                    ffma2(a2, wreg[32 + 4 * k + 2], hB.x);
                    ffma2(a3, wreg[32 + 4 * k + 3], hB.y);
                }
                float2 f0 = unpack2f(a0), f1 = unpack2f(a1);
                float2 f2 = unpack2f(a2), f3 = unpack2f(a3);
                float g = ((f0.x + f0.y) + (f1.x + f1.y)) + ((f2.x + f2.y) + (f3.x + f3.y));
                float act = (q == 2) ? tanh_f(g) : sig_f(g);
                const int base = lane & ~3;
                float fi = __shfl_sync(0xffffffffu, act, base + 0);
                float ff = __shfl_sync(0xffffffffu, act, base + 1);
                float fg = __shfl_sync(0xffffffffu, act, base + 2);
                float fo = __shfl_sync(0xffffffffu, act, base + 3);
                if (q == 0) {
                    float c = ff * cst + fi * fg;
                    float h = fo * tanh_f(c);
                    cst = c;
                    h2s[buf ^ 1][j] = h;
                    st[tp * 192 + 128 + j] = h;
                    st[tp * 192 + 160 + j] = c;
                }
            }
            __syncthreads();
        }
        __threadfence();
        __syncthreads();
        if (tid == 0) st_rel(&g_prog[b], 256);
        return;
    }

    // ---------------- worker: pull items from the queue ----------------
    __shared__ int s_item;
    for (;;) {
        __syncthreads();
        if (tid == 0) s_item = atomicAdd(&g_next, 1);
        __syncthreads();
        const int item = s_item;
        if (item >= 896) return;

        if (item < 256) {
            // mlp90: first-half tiles (even), interleaved by tile, then odd
            int tile, s;
            if (item < 128) { tile = 2 * (item & 7); s = item >> 3; }
            else { tile = 2 * ((item - 128) & 7) + 1; s = (item - 128) >> 3; }
            mlp_body<90, 90>(sm, tid, tile, s, pooled, 90, 0, false, spp_w, spp_b, fc7);
            if (tid == 0) atomicAdd(&g_done90[tile], 1);
        } else if (item < 384) {
            // reduce_xp chunk, interleaved across batches
            const int jj = item - 256;
            int c;
            if (jj < 64) c = 16 * (jj & 7) + (jj >> 3);
            else c = 16 * ((jj - 64) & 7) + 8 + ((jj - 64) >> 3);
            const int tile = c >> 3;
            const int r0 = c * 16;
            while (ld_acq(&g_done90[tile]) < 16) __nanosleep(256);
            float* embS = sm;   // [16][66]
            if (tid < 256) {
                int r = tid >> 4, ng = tid & 15;
                float4 acc = *(const float4*)&fc7_b[ng * 4];
#pragma unroll
                for (int ss = 0; ss < SPLITS; ss++) {
                    float4 v = __ldcg((const float4*)&g_part[((size_t)ss * NROWS + r0 + r) * 64 + ng * 4]);
                    acc.x += v.x; acc.y += v.y; acc.z += v.z; acc.w += v.w;
                }
                embS[r * 66 + ng * 4 + 0] = fmaxf(acc.x, 0.f);
                embS[r * 66 + ng * 4 + 1] = fmaxf(acc.y, 0.f);
                embS[r * 66 + ng * 4 + 2] = fmaxf(acc.z, 0.f);
                embS[r * 66 + ng * 4 + 3] = fmaxf(acc.w, 0.f);
            }
            __syncthreads();
            if (tid < 256) {
                ull w[32];
#pragma unroll
                for (int k = 0; k < 32; k++) w[k] = g_wc1P[k * 256 + tid];
                const float bias = g_b1c[tid];
                for (int r = 0; r < 16; r += 2) {
                    ull a0 = pack2f(bias, 0.f), a1 = 0ull;
                    ull c0 = pack2f(bias, 0.f), c1 = 0ull;
#pragma unroll
                    for (int k = 0; k < 16; k++) {
                        ffma2(a0, w[2 * k],     *(const ull*)&embS[r * 66 + 4 * k]);
                        ffma2(a1, w[2 * k + 1], *(const ull*)&embS[r * 66 + 4 * k + 2]);
                        ffma2(c0, w[2 * k],     *(const ull*)&embS[(r + 1) * 66 + 4 * k]);
                        ffma2(c1, w[2 * k + 1], *(const ull*)&embS[(r + 1) * 66 + 4 * k + 2]);
                    }
                    float2 f0 = unpack2f(a0), f1 = unpack2f(a1);
                    float2 g0 = unpack2f(c0), g1 = unpack2f(c1);
                    g_XP[(size_t)(r0 + r) * 256 + tid]     = (f0.x + f0.y) + (f1.x + f1.y);
                    g_XP[(size_t)(r0 + r + 1) * 256 + tid] = (g0.x + g0.y) + (g1.x + g1.y);
                }
            }
            __threadfence();
            __syncthreads();
            if (tid == 0) st_rel(&g_doneRX[c], 1);
        } else if (item < 640) {
            // mlp32 tile
            const int m = item - 384;
            const int u = m >> 4;
            const int tile = (u < 8) ? (2 * u) : (2 * (u - 8) + 1);
            const int s = m & 15;
            const int m0 = tile * 128;
            const int b = m0 >> 8;
            const int needed = (m0 & 255) + 128;
            while (ld_acq(&g_prog[b]) < needed) __nanosleep(256);
            mlp_body<32, 34>(sm, tid, tile, s, g_states, 192, 128, true, g_G, g_cvec, fc7);
            if (tid == 0) atomicAdd(&g_done32[tile], 1);
        } else if (item < 768) {
            // reduce_gates chunk
            const int c = item - 640;
            const int r0 = c * 16;
            const int tile = c >> 3;
            while (ld_acq(&g_done32[tile]) < 16) __nanosleep(256);
            float* S = sm;   // [16][132]
            if (tid < 256) {
                int r = tid >> 4, ng = tid & 15;
                float4 acc = *(const float4*)&fc7_b[ng * 4];
#pragma unroll
                for (int ss = 0; ss < SPLITS; ss++) {
                    float4 v = __ldcg((const float4*)&g_part[((size_t)ss * NROWS + r0 + r) * 64 + ng * 4]);
                    acc.x += v.x; acc.y += v.y; acc.z += v.z; acc.w += v.w;
                }
                S[r * 132 + ng * 4 + 0] = fmaxf(acc.x, 0.f);
                S[r * 132 + ng * 4 + 1] = fmaxf(acc.y, 0.f);
                S[r * 132 + ng * 4 + 2] = fmaxf(acc.z, 0.f);
                S[r * 132 + ng * 4 + 3] = fmaxf(acc.w, 0.f);
                float4 h = __ldcg((const float4*)&g_states[(size_t)(r0 + r) * 192 + ng * 4]);
                *(float4*)&S[r * 132 + 64 + ng * 4] = h;
            }
            __syncthreads();
            if (tid < 256) {
                ull wc[64];
#pragma unroll
                for (int k = 0; k < 64; k++) wc[k] = g_wc1P[k * 256 + tid];
                const float bias = g_b1c[tid];
                for (int r = 0; r < 16; r += 2) {
                    ull a0 = pack2f(bias, 0.f), a1 = 0ull;
                    ull c0 = pack2f(bias, 0.f), c1 = 0ull;
#pragma unroll
                    for (int k = 0; k < 32; k++) {
                        ffma2(a0, wc[2 * k],     *(const ull*)&S[r * 132 + 4 * k]);
                        ffma2(a1, wc[2 * k + 1], *(const ull*)&S[r * 132 + 4 * k + 2]);
                        ffma2(c0, wc[2 * k],     *(const ull*)&S[(r + 1) * 132 + 4 * k]);
                        ffma2(c1, wc[2 * k + 1], *(const ull*)&S[(r + 1) * 132 + 4 * k + 2]);
                    }
                    float2 f0 = unpack2f(a0), f1 = unpack2f(a1);
                    float2 g0 = unpack2f(c0), g1 = unpack2f(c1);
                    g_XP[(size_t)(r0 + r) * 256 + tid]     = (f0.x + f0.y) + (f1.x + f1.y);
                    g_XP[(size_t)(r0 + r + 1) * 256 + tid] = (g0.x + g0.y) + (g1.x + g1.y);
                }
            }
            __threadfence();
            __syncthreads();
            if (tid == 0) st_rel(&g_doneRG[c], 1);
        } else {
            // tail chunk
            const int c = item - 768;
            const int r0 = c * 16;
            float* fwS = sm;                  // [90][34]
            float* fh1 = sm + 90 * 34;        // 64
            float* th2s = fh1 + 64;           // 32
            float* tc2s = th2s + 32;          // 32
            float* gs = tc2s + 32;            // 128
            for (int idx = tid; idx < 2880; idx += 384)
                fwS[(idx >> 5) * 34 + (idx & 31)] = fw[idx];
            while (ld_acq(&g_doneRG[c]) < 1) __nanosleep(256);
            float wcat[96];
            float fwr[32];
            float b2 = 0.f, w8 = 0.f;
            const int po = tid - 32;
            if (tid < 128) {
#pragma unroll
                for (int k = 0; k < 96; k++) wcat[k] = g_wc2Pf[k * 128 + tid];
                b2 = g_b2c[tid];
                if (tid < 32) w8 = fc8w[tid];
            }
            __syncthreads();
            if (po >= 0 && po < 90) {
#pragma unroll
                for (int k = 0; k < 32; k++) fwr[k] = fwS[po * 34 + k];
            }
            const float b8 = fc8b[0];
            const bool is_tanh2 = (tid >= 64 && tid < 96);
            for (int r = 0; r < 16; r++) {
                const int row = r0 + r;
                const float* xpf = g_XP + (size_t)row * 256;
                const float* st = g_states + (size_t)row * 192;
                if (tid < 64) {
                    float i = sig_f(__ldcg(&xpf[tid]));
                    float f = sig_f(__ldcg(&xpf[64 + tid]));
                    float gg = tanh_f(__ldcg(&xpf[128 + tid]));
                    float o = sig_f(__ldcg(&xpf[192 + tid]));
                    float cn = f * __ldcg(&st[64 + tid]) + i * gg;
                    fh1[tid] = o * tanh_f(cn);
                } else if (tid < 96) {
                    th2s[tid - 64] = __ldcg(&st[128 + (tid - 64)]);
                } else if (tid < 128) {
                    tc2s[tid - 96] = __ldcg(&st[160 + (tid - 96)]);
                }
                __syncthreads();
                if (tid < 128) {
                    float a = b2;
#pragma unroll
                    for (int k = 0; k < 64; k++) a += wcat[k] * fh1[k];
#pragma unroll
                    for (int k = 0; k < 32; k++) a += wcat[64 + k] * th2s[k];
                    gs[tid] = is_tanh2 ? tanh_f(a) : sig_f(a);
                }
                __syncthreads();
                if (tid < 32) {
                    float cn = gs[32 + tid] * tc2s[tid] + gs[tid] * gs[64 + tid];
                    float fh2 = gs[96 + tid] * tanh_f(cn);
                    float v1 = th2s[tid] * w8;
                    float v2 = fh2 * w8;
#pragma unroll
                    for (int off = 16; off > 0; off >>= 1) {
                        v1 += __shfl_down_sync(0xffffffffu, v1, off);
                        v2 += __shfl_down_sync(0xffffffffu, v2, off);
                    }
                    if (tid == 0) {
                        out[row] = sig_f(v1 + b8);
                        out[NROWS + row] = sig_f(v2 + b8);
                    }
                } else if (po >= 0 && po < 90) {
                    float s2 = fb[po];
#pragma unroll
                    for (int k = 0; k < 32; k++) s2 += fwr[k] * th2s[k];
                    fpooled[(size_t)row * 90 + po] = s2;
                }
                __syncthreads();
            }
        }
    }
}

// ---------------- host ----------------
extern "C" void kernel_launch(void* const* d_in, const int* in_sizes, int n_in,
                              void* d_out, int out_size) {
    const float* frames = (const float*)d_in[0];
    const float* spp_w  = (const float*)d_in[1];
    const float* spp_b  = (const float*)d_in[2];
    const float* fc7_w  = (const float*)d_in[3];
    const float* fc7_b  = (const float*)d_in[4];
    const float* w1i    = (const float*)d_in[5];
    const float* w1h    = (const float*)d_in[6];
    const float* b1i    = (const float*)d_in[7];
    const float* b1h    = (const float*)d_in[8];
    const float* w2i    = (const float*)d_in[9];
    const float* w2h    = (const float*)d_in[10];
    const float* b2i    = (const float*)d_in[11];
    const float* b2h    = (const float*)d_in[12];
    const float* fw     = (const float*)d_in[13];
    const float* fb     = (const float*)d_in[14];
    const float* fc8w   = (const float*)d_in[15];
    const float* fc8b   = (const float*)d_in[16];
    float* out = (float*)d_out;

    float* STATES;
    cudaGetSymbolAddress((void**)&STATES, g_states);
    (void)STATES;

    const int SMM = (128 * 90 + 32 * 90 + 64 * 36 + 128 * 40) * 4;   // 87296 (mlp90 role)
    cudaFuncSetAttribute(mega, cudaFuncAttributeMaxDynamicSharedMemorySize, SMM);

    float* pooled  = out + 2 * NROWS;
    float* fpooled = out + 2 * NROWS + NROWS * 90;

    spp_prep<<<6677, 256>>>(frames, pooled, spp_w, spp_b, fw, fb,
                            b1i, b1h, w1i, w1h, w2i, w2h, b2i, b2h);
    mega<<<148, 384, SMM>>>(pooled, spp_w, spp_b, fc7_w, fc7_b,
                            fc8w, fc8b, fw, fb, out, fpooled);
}

// round 16
// speedup vs baseline: 1.1576x; 1.1576x over previous
#include <cuda_runtime.h>
#include <cuda_bf16.h>
#include <math.h>

#define NROWS 2048
#define EMBED 4096
#define SPLITS 16

typedef unsigned long long ull;

__device__ __forceinline__ void ffma2(ull& d, ull a, ull b) {
    asm("fma.rn.f32x2 %0, %1, %2, %3;" : "=l"(d) : "l"(a), "l"(b), "l"(d));
}
__device__ __forceinline__ ull pack2f(float x, float y) {
    ull r; asm("mov.b64 %0, {%1, %2};" : "=l"(r) : "f"(x), "f"(y)); return r;
}
__device__ __forceinline__ float2 unpack2f(ull v) {
    float2 f; asm("mov.b64 {%0, %1}, %2;" : "=f"(f.x), "=f"(f.y) : "l"(v)); return f;
}
__device__ __forceinline__ int ld_acq(const int* p) {
    int v; asm volatile("ld.acquire.gpu.global.b32 %0, [%1];" : "=r"(v) : "l"(p)); return v;
}
__device__ __forceinline__ void st_rel(int* p, int v) {
    asm volatile("st.release.gpu.global.b32 [%0], %1;" :: "l"(p), "r"(v));
}

// ---------------- scratch ----------------
__device__ float g_part[SPLITS * NROWS * 64];
__device__ float g_XP[NROWS * 256];
__device__ float g_states[NROWS * 192];
__device__ float g_G[EMBED * 32];
__device__ float g_cvec[EMBED];
__device__ float g_b1c[256];
__device__ float g_b2c[128];
__device__ ull g_w1hP[32 * 256];
__device__ ull g_w2P[48 * 128];
__device__ ull g_wc1P[64 * 256];
__device__ float g_wc2Pf[96 * 128];
// flags
__device__ int g_prog[8];
__device__ int g_doneSPP[16];
__device__ int g_done90[16];
__device__ int g_doneRX[128];
__device__ int g_done32[16];
__device__ int g_doneRG[128];
__device__ int g_donePrep;

__device__ __forceinline__ float sig_f(float x) {
    return __fdividef(1.0f, 1.0f + __expf(-x));
}
__device__ __forceinline__ float tanh_f(float x) {
    return __fdividef(2.0f, 1.0f + __expf(-2.0f * x)) - 1.0f;
}

// ---------------- flag reset (replay-safe) ----------------
__global__ void reset_flags() {
    const int tid = threadIdx.x;
    if (tid < 8) g_prog[tid] = 0;
    if (tid < 16) { g_doneSPP[tid] = 0; g_done90[tid] = 0; g_done32[tid] = 0; }
    if (tid < 128) { g_doneRX[tid] = 0; g_doneRG[tid] = 0; }
    if (tid == 0) g_donePrep = 0;
}

// ---------------- shared mlp body ----------------
template<int KA, int KAP>
__device__ __forceinline__ void mlp_body(
        float* sm, int tid, int tile, int s,
        const float* __restrict__ Asrc, int lda, int aoff,
        const float* __restrict__ W1, const float* __restrict__ b1,
        const float* __restrict__ fc7) {
    constexpr int WS = KAP;
    constexpr int NW = (32 * KA + 255) / 256;
    float* A2 = sm;
    float* W2 = A2 + 128 * KAP;
    float* F2 = W2 + 32 * WS;
    float* Es = F2 + 64 * 36;
    const int m0 = tile * 128;
    for (int idx = tid; idx < 128 * KA; idx += 384) {
        int rr = idx / KA, p = idx - rr * KA;
        A2[rr * KAP + p] = __ldcg(&Asrc[(size_t)(m0 + rr) * lda + aoff + p]);
    }
    ull acc2[8][4];
#pragma unroll
    for (int i = 0; i < 8; i++)
#pragma unroll
        for (int j = 0; j < 4; j++) acc2[i][j] = 0ull;
    const int kbase = s * 256;
    const int txE = tid & 7, tyE = tid >> 3;
    const int txM = tid & 15, tyM = tid >> 4;
    const int eswM = 4 * (tyM & 7);
    const int fswM = 4 * (txM & 7);
    float pw[NW], pf[8];
    if (tid < 256) {
#pragma unroll
        for (int i = 0; i < NW; i++) {
            int idx = tid + i * 256;
            if (idx < 32 * KA) pw[i] = W1[(size_t)(kbase + idx / KA) * KA + idx % KA];
        }
#pragma unroll
        for (int i = 0; i < 8; i++) {
            int idx = tid + i * 256;
            pf[i] = fc7[(size_t)(idx >> 5) * 4096 + kbase + (idx & 31)];
        }
    }
    for (int kc = 0; kc < 256; kc += 32) {
        const int cg0 = kbase + kc;
        __syncthreads();
        if (tid < 256) {
#pragma unroll
            for (int i = 0; i < NW; i++) {
                int idx = tid + i * 256;
                if (idx < 32 * KA) W2[(idx / KA) * WS + idx % KA] = pw[i];
            }
#pragma unroll
            for (int i = 0; i < 8; i++) {
                int idx = tid + i * 256;
                int n = idx >> 5, kk = idx & 31;
                F2[n * 36 + (kk ^ (4 * ((n >> 2) & 7)))] = pf[i];
            }
        }
        __syncthreads();
        if (tid < 256) {
            if (kc + 32 < 256) {
                const int ng0 = cg0 + 32;
#pragma unroll
                for (int i = 0; i < NW; i++) {
                    int idx = tid + i * 256;
                    if (idx < 32 * KA) pw[i] = W1[(size_t)(ng0 + idx / KA) * KA + idx % KA];
                }
#pragma unroll
                for (int i = 0; i < 8; i++) {
                    int idx = tid + i * 256;
                    pf[i] = fc7[(size_t)(idx >> 5) * 4096 + ng0 + (idx & 31)];
                }
            }
            ull e2[4][4];
#pragma unroll
            for (int i = 0; i < 4; i++)
#pragma unroll
                for (int j = 0; j < 4; j++) e2[i][j] = 0ull;
#pragma unroll 15
            for (int p = 0; p < KA; p += 2) {
                ull a0 = *(const ull*)&A2[(tyE * 4 + 0) * KAP + p];
                ull a1 = *(const ull*)&A2[(tyE * 4 + 1) * KAP + p];
                ull a2 = *(const ull*)&A2[(tyE * 4 + 2) * KAP + p];
                ull a3 = *(const ull*)&A2[(tyE * 4 + 3) * KAP + p];
                ull w0 = *(const ull*)&W2[(txE * 4 + 0) * WS + p];
                ull w1 = *(const ull*)&W2[(txE * 4 + 1) * WS + p];
                ull w2 = *(const ull*)&W2[(txE * 4 + 2) * WS + p];
                ull w3 = *(const ull*)&W2[(txE * 4 + 3) * WS + p];
                ffma2(e2[0][0], a0, w0); ffma2(e2[0][1], a0, w1);
                ffma2(e2[0][2], a0, w2); ffma2(e2[0][3], a0, w3);
                ffma2(e2[1][0], a1, w0); ffma2(e2[1][1], a1, w1);
                ffma2(e2[1][2], a1, w2); ffma2(e2[1][3], a1, w3);
                ffma2(e2[2][0], a2, w0); ffma2(e2[2][1], a2, w1);
                ffma2(e2[2][2], a2, w2); ffma2(e2[2][3], a2, w3);
                ffma2(e2[3][0], a3, w0); ffma2(e2[3][1], a3, w1);
                ffma2(e2[3][2], a3, w2); ffma2(e2[3][3], a3, w3);
            }
#pragma unroll
            for (int i = 0; i < 4; i++) {
                int rr = tyE * 4 + i;
                int swz = 4 * ((rr >> 3) & 7);
#pragma unroll
                for (int j = 0; j < 4; j++) {
                    int c = txE * 4 + j;
                    float2 f = unpack2f(e2[i][j]);
                    float v = f.x + f.y + b1[cg0 + c];
                    Es[rr * 40 + (c ^ swz)] = fmaxf(v, 0.f);
                }
            }
        }
        __syncthreads();
        if (tid < 256) {
#pragma unroll
            for (int kk = 0; kk < 32; kk += 2) {
                ull e[8], fv[4];
#pragma unroll
                for (int i = 0; i < 8; i++)
                    e[i] = *(const ull*)&Es[(tyM * 8 + i) * 40 + (kk ^ eswM)];
#pragma unroll
                for (int j = 0; j < 4; j++)
                    fv[j] = *(const ull*)&F2[(txM * 4 + j) * 36 + (kk ^ fswM)];
#pragma unroll
                for (int i = 0; i < 8; i++)
#pragma unroll
                    for (int j = 0; j < 4; j++) ffma2(acc2[i][j], e[i], fv[j]);
            }
        }
    }
    if (tid < 256) {
#pragma unroll
        for (int i = 0; i < 8; i++)
#pragma unroll
            for (int j = 0; j < 4; j++) {
                float2 f = unpack2f(acc2[i][j]);
                g_part[((size_t)s * NROWS + m0 + tyM * 8 + i) * 64 + txM * 4 + j] = f.x + f.y;
            }
    }
    __threadfence();
    __syncthreads();
}

// rx (reduce_xp) body shared
__device__ __forceinline__ void rx_body(float* sm, int tid, int c,
                                        const float* __restrict__ fc7_b) {
    const int tile = c >> 3;
    const int r0 = c * 16;
    while (ld_acq(&g_done90[tile]) < 16) __nanosleep(256);
    float* embS = sm;   // [16][66]
    if (tid < 256) {
        int r = tid >> 4, ng = tid & 15;
        float4 acc = *(const float4*)&fc7_b[ng * 4];
#pragma unroll
        for (int ss = 0; ss < SPLITS; ss++) {
            float4 v = __ldcg((const float4*)&g_part[((size_t)ss * NROWS + r0 + r) * 64 + ng * 4]);
            acc.x += v.x; acc.y += v.y; acc.z += v.z; acc.w += v.w;
        }
        embS[r * 66 + ng * 4 + 0] = fmaxf(acc.x, 0.f);
        embS[r * 66 + ng * 4 + 1] = fmaxf(acc.y, 0.f);
        embS[r * 66 + ng * 4 + 2] = fmaxf(acc.z, 0.f);
        embS[r * 66 + ng * 4 + 3] = fmaxf(acc.w, 0.f);
    }
    __syncthreads();
    if (tid < 256) {
        ull w[32];
#pragma unroll
        for (int k = 0; k < 32; k++) w[k] = g_wc1P[k * 256 + tid];
        const float bias = g_b1c[tid];
        for (int r = 0; r < 16; r += 2) {
            ull a0 = pack2f(bias, 0.f), a1 = 0ull;
            ull c0 = pack2f(bias, 0.f), c1 = 0ull;
#pragma unroll
            for (int k = 0; k < 16; k++) {
                ffma2(a0, w[2 * k],     *(const ull*)&embS[r * 66 + 4 * k]);
                ffma2(a1, w[2 * k + 1], *(const ull*)&embS[r * 66 + 4 * k + 2]);
                ffma2(c0, w[2 * k],     *(const ull*)&embS[(r + 1) * 66 + 4 * k]);
                ffma2(c1, w[2 * k + 1], *(const ull*)&embS[(r + 1) * 66 + 4 * k + 2]);
            }
            float2 f0 = unpack2f(a0), f1 = unpack2f(a1);
            float2 g0 = unpack2f(c0), g1 = unpack2f(c1);
            g_XP[(size_t)(r0 + r) * 256 + tid]     = (f0.x + f0.y) + (f1.x + f1.y);
            g_XP[(size_t)(r0 + r + 1) * 256 + tid] = (g0.x + g0.y) + (g1.x + g1.y);
        }
    }
    __threadfence();
    __syncthreads();
    if (tid == 0) st_rel(&g_doneRX[c], 1);
}

// ================= MEGA: whole net after flag reset, one launch =================
// 0-532 prep | 533-2068 spp even | 2069-2196 mlp90 even | 2197-2260 rx even |
// 2261-2268 scan | 2269-3804 spp odd | 3805-3932 mlp90 odd | 3933-3996 rx odd |
// 3997-4252 mlp32 | 4253-4380 RG | 4381-4508 tail
__global__ void __launch_bounds__(384, 1) mega(
        const float* __restrict__ frames, float* __restrict__ pooled,
        const float* __restrict__ spp_w, const float* __restrict__ spp_b,
        const float* __restrict__ fw, const float* __restrict__ fb,
        const float* __restrict__ b1i, const float* __restrict__ b1h,
        const float* __restrict__ w1i, const float* __restrict__ w1h,
        const float* __restrict__ w2i, const float* __restrict__ w2h,
        const float* __restrict__ b2i, const float* __restrict__ b2h,
        const float* __restrict__ fc7, const float* __restrict__ fc7_b,
        const float* __restrict__ fc8w, const float* __restrict__ fc8b,
        float* __restrict__ out, float* __restrict__ fpooled) {
    extern __shared__ float sm[];
    const int blk = blockIdx.x;
    const int tid = threadIdx.x;

    if (blk < 533) {
        // ---------------- prep roles ----------------
        if (blk < 512) {
            if (tid < 256) {
                int o = blk * 256 + tid;
                int i = o >> 5, j = o & 31;
                float s = 0.f;
                for (int p = 0; p < 90; p++) s += spp_w[i * 90 + p] * fw[p * 32 + j];
                g_G[o] = s;
            }
        } else if (blk < 528) {
            if (tid < 256) {
                int i = (blk - 512) * 256 + tid;
                float s = spp_b[i];
                for (int p = 0; p < 90; p++) s += spp_w[i * 90 + p] * fb[p];
                g_cvec[i] = s;
            }
        } else if (blk == 528) {
            if (tid < 256) g_b1c[tid] = b1i[tid] + b1h[tid];
            if (tid < 128) g_b2c[tid] = b2i[tid] + b2h[tid];
        } else if (blk == 529) {
            for (int idx = tid; idx < 8192; idx += 384) {
                int k = idx >> 8, r = idx & 255;
                g_w1hP[idx] = pack2f(w1h[r * 64 + 2 * k], w1h[r * 64 + 2 * k + 1]);
            }
        } else if (blk == 530) {
            for (int idx = tid; idx < 6144; idx += 384) {
                int k = idx >> 7, r = idx & 127;
                ull v;
                if (k < 32) v = pack2f(w2i[r * 64 + 2 * k], w2i[r * 64 + 2 * k + 1]);
                else { int k2 = k - 32; v = pack2f(w2h[r * 32 + 2 * k2], w2h[r * 32 + 2 * k2 + 1]); }
                g_w2P[idx] = v;
            }
        } else if (blk == 531) {
            for (int idx = tid; idx < 16384; idx += 384) {
                int k = idx >> 8, r = idx & 255;
                ull v;
                if (k < 32) v = pack2f(w1i[r * 64 + 2 * k], w1i[r * 64 + 2 * k + 1]);
                else { int k2 = k - 32; v = pack2f(w1h[r * 64 + 2 * k2], w1h[r * 64 + 2 * k2 + 1]); }
                g_wc1P[idx] = v;
            }
        } else {
            for (int idx = tid; idx < 12288; idx += 384) {
                int k = idx >> 7, g = idx & 127;
                g_wc2Pf[idx] = (k < 64) ? w2i[g * 64 + k] : w2h[g * 32 + (k - 64)];
            }
        }
        __threadfence();
        __syncthreads();
        if (tid == 0) atomicAdd(&g_donePrep, 1);
        return;
    }

    if ((blk >= 533 && blk < 2069) || (blk >= 2269 && blk < 3805)) {
        // ---------------- SPP role: 2 image-channels per block ----------------
        __shared__ float tmax2[2][144];
        const int p = (blk < 2069) ? (blk - 533) : (blk - 2269);
        const bool even = (blk < 2069);
        const int tileIdx = p / 192;
        const int tile = even ? 2 * tileIdx : 2 * tileIdx + 1;
        const int within = p - tileIdx * 192;
        const int nc0 = tile * 384 + 2 * within;
        const int grp = tid / 192, lt = tid - grp * 192;
        const int nc = nc0 + grp;
        if (lt < 144) {
            const float* img = frames + (size_t)nc * 9216;
            const int ti = lt / 12, tj = lt % 12;
            const float* pp = img + ti * 8 * 96 + tj * 8;
            float m = -3.402823466e38f;
#pragma unroll
            for (int r = 0; r < 8; r++) {
                float4 v0 = *(const float4*)(pp + r * 96);
                float4 v1 = *(const float4*)(pp + r * 96 + 4);
                m = fmaxf(m, fmaxf(fmaxf(v0.x, v0.y), fmaxf(v0.z, v0.w)));
                m = fmaxf(m, fmaxf(fmaxf(v1.x, v1.y), fmaxf(v1.z, v1.w)));
            }
            tmax2[grp][lt] = m;
        }
        __syncthreads();
        {
            const float* tmax = tmax2[grp];
            const int n = nc / 3, c = nc - 3 * n;
            float* orow = pooled + (size_t)n * 90;
            if (lt < 16) {
                int i = lt / 4, j = lt % 4;
                float m = -3.402823466e38f;
                for (int a = 0; a < 3; a++) for (int b = 0; b < 3; b++)
                    m = fmaxf(m, tmax[(i * 3 + a) * 12 + (j * 3 + b)]);
                orow[c * 16 + i * 4 + j] = m;
            } else if (lt < 25) {
                int q = lt - 16, i = q / 3, j = q % 3;
                float m = -3.402823466e38f;
                for (int a = 0; a < 4; a++) for (int b = 0; b < 4; b++)
                    m = fmaxf(m, tmax[(i * 4 + a) * 12 + (j * 4 + b)]);
                orow[48 + c * 9 + i * 3 + j] = m;
            } else if (lt < 29) {
                int q = lt - 25, i = q / 2, j = q % 2;
                float m = -3.402823466e38f;
                for (int a = 0; a < 6; a++) for (int b = 0; b < 6; b++)
                    m = fmaxf(m, tmax[(i * 6 + a) * 12 + (j * 6 + b)]);
                orow[75 + c * 4 + i * 2 + j] = m;
            } else if (lt == 29) {
                float m = -3.402823466e38f;
                for (int a = 0; a < 144; a++) m = fmaxf(m, tmax[a]);
                orow[87 + c] = m;
            }
        }
        __threadfence();
        __syncthreads();
        if (tid == 0) atomicAdd(&g_doneSPP[tile], 1);
        return;
    }

    if ((blk >= 2069 && blk < 2197) || (blk >= 3805 && blk < 3933)) {
        // ---------------- mlp90 role ----------------
        const int idx0 = (blk < 2197) ? (blk - 2069) : (blk - 3805);
        const int tile = (blk < 2197) ? 2 * (idx0 >> 4) : 2 * (idx0 >> 4) + 1;
        const int s = idx0 & 15;
        while (ld_acq(&g_doneSPP[tile]) < 192) __nanosleep(256);
        mlp_body<90, 90>(sm, tid, tile, s, pooled, 90, 0, spp_w, spp_b, fc7);
        if (tid == 0) atomicAdd(&g_done90[tile], 1);
        return;
    }

    if ((blk >= 2197 && blk < 2261) || (blk >= 3933 && blk < 3997)) {
        // ---------------- reduce_xp role; order: k outer, batch inner ----------------
        while (ld_acq(&g_donePrep) < 533) __nanosleep(256);
        const int idx0 = (blk < 2261) ? (blk - 2197) : (blk - 3933);
        const int k = idx0 >> 3, b = idx0 & 7;
        const int c = 16 * b + ((blk < 2261) ? k : (8 + k));
        rx_body(sm, tid, c, fc7_b);
        return;
    }

    if (blk >= 2261 && blk < 2269) {
        // ---------------- scan role ----------------
        while (ld_acq(&g_donePrep) < 533) __nanosleep(256);
        __shared__ __align__(16) float h1s[2][64];
        __shared__ __align__(16) float h2s[2][32];
        const int wid = tid >> 5, lane = tid & 31;
        const int b = blk - 2261;
        const float* xp = g_XP + (size_t)b * 65536;
        float* st = g_states + (size_t)b * 49152;
        ull wreg[48];
        float bc2 = 0.f, cst = 0.f;
        const int q = lane & 3;
        int j, r;
        if (wid < 8) {
            j = (wid << 3) + (lane >> 2);
            r = (q << 6) + j;
#pragma unroll
            for (int k = 0; k < 32; k++) wreg[k] = g_w1hP[k * 256 + r];
        } else {
            j = ((wid - 8) << 3) + (lane >> 2);
            r = (q << 5) + j;
#pragma unroll
            for (int k = 0; k < 48; k++) wreg[k] = g_w2P[k * 128 + r];
            bc2 = g_b2c[r];
        }
        if (tid < 64) { h1s[0][tid] = 0.f; h1s[1][tid] = 0.f; }
        if (tid >= 64 && tid < 96) { h2s[0][tid - 64] = 0.f; h2s[1][tid - 64] = 0.f; }
        while (ld_acq(&g_doneRX[16 * b]) < 1) __nanosleep(256);
        float xcur = 0.f, x1 = 0.f;
        if (wid < 8) { xcur = __ldcg(&xp[r]); x1 = __ldcg(&xp[256 + r]); }
        __syncthreads();
        for (int t = 0; t <= 256; t++) {
            if ((t & 31) == 0 && t) {
                __threadfence();
                __syncthreads();
                if (tid == 0) st_rel(&g_prog[b], t - 1);
            }
            const int buf = t & 1;
            if (wid < 8) {
                if (t < 256) {
                    float x2 = 0.f;
                    const int row2 = t + 2;
                    if (row2 < 256) {
                        if ((row2 & 15) == 0) {
                            while (ld_acq(&g_doneRX[16 * b + (row2 >> 4)]) < 1) __nanosleep(128);
                        }
                        x2 = __ldcg(&xp[row2 * 256 + r]);
                    }
                    const float* hb = h1s[buf];
                    ull a0 = pack2f(xcur, 0.f), a1 = 0ull, a2 = 0ull, a3 = 0ull;
#pragma unroll
                    for (int k = 0; k < 8; k++) {
                        ulonglong2 hA = *(const ulonglong2*)&hb[8 * k + 0];
                        ulonglong2 hB = *(const ulonglong2*)&hb[8 * k + 4];
                        ffma2(a0, wreg[4 * k + 0], hA.x);
                        ffma2(a1, wreg[4 * k + 1], hA.y);
                        ffma2(a2, wreg[4 * k + 2], hB.x);
                        ffma2(a3, wreg[4 * k + 3], hB.y);
                    }
                    float2 f0 = unpack2f(a0), f1 = unpack2f(a1);
                    float2 f2 = unpack2f(a2), f3 = unpack2f(a3);
                    float g = ((f0.x + f0.y) + (f1.x + f1.y)) + ((f2.x + f2.y) + (f3.x + f3.y));
                    float act = (q == 2) ? tanh_f(g) : sig_f(g);
                    const int base = lane & ~3;
                    float fi = __shfl_sync(0xffffffffu, act, base + 0);
                    float ff = __shfl_sync(0xffffffffu, act, base + 1);
                    float fg = __shfl_sync(0xffffffffu, act, base + 2);
                    float fo = __shfl_sync(0xffffffffu, act, base + 3);
                    if (q == 0) {
                        float c = ff * cst + fi * fg;
                        float h = fo * tanh_f(c);
                        cst = c;
                        h1s[buf ^ 1][j] = h;
                        st[t * 192 + j] = h;
                        st[t * 192 + 64 + j] = c;
                    }
                    xcur = x1; x1 = x2;
                }
            } else if (t >= 1) {
                const int tp = t - 1;
                const float* hb1 = h1s[buf];
                const float* hb2 = h2s[buf];
                ull a0 = pack2f(bc2, 0.f), a1 = 0ull, a2 = 0ull, a3 = 0ull;
#pragma unroll
                for (int k = 0; k < 8; k++) {
                    ulonglong2 hA = *(const ulonglong2*)&hb1[8 * k + 0];
                    ulonglong2 hB = *(const ulonglong2*)&hb1[8 * k + 4];
                    ffma2(a0, wreg[4 * k + 0], hA.x);
                    ffma2(a1, wreg[4 * k + 1], hA.y);
                    ffma2(a2, wreg[4 * k + 2], hB.x);
                    ffma2(a3, wreg[4 * k + 3], hB.y);
                }
#pragma unroll
                for (int k = 0; k < 4; k++) {
                    ulonglong2 hA = *(const ulonglong2*)&hb2[8 * k + 0];
                    ulonglong2 hB = *(const ulonglong2*)&hb2[8 * k + 4];
                    ffma2(a0, wreg[32 + 4 * k + 0], hA.x);
                    ffma2(a1, wreg[32 + 4 * k + 1], hA.y);
                    ffma2(a2, wreg[32 + 4 * k + 2], hB.x);
                    ffma2(a3, wreg[32 + 4 * k + 3], hB.y);
                }
                float2 f0 = unpack2f(a0), f1 = unpack2f(a1);
                float2 f2 = unpack2f(a2), f3 = unpack2f(a3);
                float g = ((f0.x + f0.y) + (f1.x + f1.y)) + ((f2.x + f2.y) + (f3.x + f3.y));
                float act = (q == 2) ? tanh_f(g) : sig_f(g);
                const int base = lane & ~3;
                float fi = __shfl_sync(0xffffffffu, act, base + 0);
                float ff = __shfl_sync(0xffffffffu, act, base + 1);
                float fg = __shfl_sync(0xffffffffu, act, base + 2);
                float fo = __shfl_sync(0xffffffffu, act, base + 3);
                if (q == 0) {
                    float c = ff * cst + fi * fg;
                    float h = fo * tanh_f(c);
                    cst = c;
                    h2s[buf ^ 1][j] = h;
                    st[tp * 192 + 128 + j] = h;
                    st[tp * 192 + 160 + j] = c;
                }
            }
            __syncthreads();
        }
        __threadfence();
        __syncthreads();
        if (tid == 0) st_rel(&g_prog[b], 256);
        return;
    }

    if (blk >= 3997 && blk < 4253) {
        // ---------------- mlp32 role ----------------
        while (ld_acq(&g_donePrep) < 533) __nanosleep(256);
        const int m = blk - 3997;
        const int u = m >> 4;
        const int tile = (u < 8) ? (2 * u) : (2 * (u - 8) + 1);
        const int s = m & 15;
        const int m0 = tile * 128;
        const int b = m0 >> 8;
        const int needed = (m0 & 255) + 128;
        while (ld_acq(&g_prog[b]) < needed) __nanosleep(256);
        mlp_body<32, 34>(sm, tid, tile, s, g_states, 192, 128, g_G, g_cvec, fc7);
        if (tid == 0) atomicAdd(&g_done32[tile], 1);
        return;
    }

    if (blk >= 4253 && blk < 4381) {
        // ---------------- reduce_gates role ----------------
        while (ld_acq(&g_donePrep) < 533) __nanosleep(256);
        float* S = sm;   // [16][132]
        const int c = blk - 4253;
        const int r0 = c * 16;
        const int tile = c >> 3;
        while (ld_acq(&g_done32[tile]) < 16) __nanosleep(256);
        if (tid < 256) {
            int r = tid >> 4, ng = tid & 15;
            float4 acc = *(const float4*)&fc7_b[ng * 4];
#pragma unroll
            for (int ss = 0; ss < SPLITS; ss++) {
                float4 v = __ldcg((const float4*)&g_part[((size_t)ss * NROWS + r0 + r) * 64 + ng * 4]);
                acc.x += v.x; acc.y += v.y; acc.z += v.z; acc.w += v.w;
            }
            S[r * 132 + ng * 4 + 0] = fmaxf(acc.x, 0.f);
            S[r * 132 + ng * 4 + 1] = fmaxf(acc.y, 0.f);
            S[r * 132 + ng * 4 + 2] = fmaxf(acc.z, 0.f);
            S[r * 132 + ng * 4 + 3] = fmaxf(acc.w, 0.f);
            float4 h = __ldcg((const float4*)&g_states[(size_t)(r0 + r) * 192 + ng * 4]);
            *(float4*)&S[r * 132 + 64 + ng * 4] = h;
        }
        __syncthreads();
        if (tid < 256) {
            ull wc[64];
#pragma unroll
            for (int k = 0; k < 64; k++) wc[k] = g_wc1P[k * 256 + tid];
            const float bias = g_b1c[tid];
            for (int r = 0; r < 16; r += 2) {
                ull a0 = pack2f(bias, 0.f), a1 = 0ull;
                ull c0 = pack2f(bias, 0.f), c1 = 0ull;
#pragma unroll
                for (int k = 0; k < 32; k++) {
                    ffma2(a0, wc[2 * k],     *(const ull*)&S[r * 132 + 4 * k]);
                    ffma2(a1, wc[2 * k + 1], *(const ull*)&S[r * 132 + 4 * k + 2]);
                    ffma2(c0, wc[2 * k],     *(const ull*)&S[(r + 1) * 132 + 4 * k]);
                    ffma2(c1, wc[2 * k + 1], *(const ull*)&S[(r + 1) * 132 + 4 * k + 2]);
                }
                float2 f0 = unpack2f(a0), f1 = unpack2f(a1);
                float2 g0 = unpack2f(c0), g1 = unpack2f(c1);
                g_XP[(size_t)(r0 + r) * 256 + tid]     = (f0.x + f0.y) + (f1.x + f1.y);
                g_XP[(size_t)(r0 + r + 1) * 256 + tid] = (g0.x + g0.y) + (g1.x + g1.y);
            }
        }
        __threadfence();
        __syncthreads();
        if (tid == 0) st_rel(&g_doneRG[c], 1);
        return;
    }

    // ---------------- tail role ----------------
    {
        while (ld_acq(&g_donePrep) < 533) __nanosleep(256);
        float* fwS = sm;                  // [90][34]
        __shared__ float fh1[64], th2s[32], tc2s[32], gs[128];
        const int c = blk - 4381;
        const int r0 = c * 16;
        for (int idx = tid; idx < 2880; idx += 384)
            fwS[(idx >> 5) * 34 + (idx & 31)] = fw[idx];
        while (ld_acq(&g_doneRG[c]) < 1) __nanosleep(256);
        float wcat[96];
        float fwr[32];
        float b2 = 0.f, w8 = 0.f;
        const int po = tid - 32;
        if (tid < 128) {
#pragma unroll
            for (int k = 0; k < 96; k++) wcat[k] = g_wc2Pf[k * 128 + tid];
            b2 = g_b2c[tid];
            if (tid < 32) w8 = fc8w[tid];
        }
        __syncthreads();
        if (po >= 0 && po < 90) {
#pragma unroll
            for (int k = 0; k < 32; k++) fwr[k] = fwS[po * 34 + k];
        }
        const float b8 = fc8b[0];
        const bool is_tanh2 = (tid >= 64 && tid < 96);
        for (int r = 0; r < 16; r++) {
            const int row = r0 + r;
            const float* xpf = g_XP + (size_t)row * 256;
            const float* st = g_states + (size_t)row * 192;
            if (tid < 64) {
                float i = sig_f(__ldcg(&xpf[tid]));
                float f = sig_f(__ldcg(&xpf[64 + tid]));
                float gg = tanh_f(__ldcg(&xpf[128 + tid]));
                float o = sig_f(__ldcg(&xpf[192 + tid]));
                float cn = f * __ldcg(&st[64 + tid]) + i * gg;
                fh1[tid] = o * tanh_f(cn);
            } else if (tid < 96) {
                th2s[tid - 64] = __ldcg(&st[128 + (tid - 64)]);
            } else if (tid < 128) {
                tc2s[tid - 96] = __ldcg(&st[160 + (tid - 96)]);
            }
            __syncthreads();
            if (tid < 128) {
                float a = b2;
#pragma unroll
                for (int k = 0; k < 64; k++) a += wcat[k] * fh1[k];
#pragma unroll
                for (int k = 0; k < 32; k++) a += wcat[64 + k] * th2s[k];
                gs[tid] = is_tanh2 ? tanh_f(a) : sig_f(a);
            }
            __syncthreads();
            if (tid < 32) {
                float cn = gs[32 + tid] * tc2s[tid] + gs[tid] * gs[64 + tid];
                float fh2 = gs[96 + tid] * tanh_f(cn);
                float v1 = th2s[tid] * w8;
                float v2 = fh2 * w8;
#pragma unroll
                for (int off = 16; off > 0; off >>= 1) {
                    v1 += __shfl_down_sync(0xffffffffu, v1, off);
                    v2 += __shfl_down_sync(0xffffffffu, v2, off);
                }
                if (tid == 0) {
                    out[row] = sig_f(v1 + b8);
                    out[NROWS + row] = sig_f(v2 + b8);
                }
            } else if (po >= 0 && po < 90) {
                float s2 = fb[po];
#pragma unroll
                for (int k = 0; k < 32; k++) s2 += fwr[k] * th2s[k];
                fpooled[(size_t)row * 90 + po] = s2;
            }
            __syncthreads();
        }
    }
}

// ---------------- host ----------------
extern "C" void kernel_launch(void* const* d_in, const int* in_sizes, int n_in,
                              void* d_out, int out_size) {
    const float* frames = (const float*)d_in[0];
    const float* spp_w  = (const float*)d_in[1];
    const float* spp_b  = (const float*)d_in[2];
    const float* fc7_w  = (const float*)d_in[3];
    const float* fc7_b  = (const float*)d_in[4];
    const float* w1i    = (const float*)d_in[5];
    const float* w1h    = (const float*)d_in[6];
    const float* b1i    = (const float*)d_in[7];
    const float* b1h    = (const float*)d_in[8];
    const float* w2i    = (const float*)d_in[9];
    const float* w2h    = (const float*)d_in[10];
    const float* b2i    = (const float*)d_in[11];
    const float* b2h    = (const float*)d_in[12];
    const float* fw     = (const float*)d_in[13];
    const float* fb     = (const float*)d_in[14];
    const float* fc8w   = (const float*)d_in[15];
    const float* fc8b   = (const float*)d_in[16];
    float* out = (float*)d_out;

    const int SMM = (128 * 90 + 32 * 90 + 64 * 36 + 128 * 40) * 4;   // 87296 (mlp90 role)
    cudaFuncSetAttribute(mega, cudaFuncAttributeMaxDynamicSharedMemorySize, SMM);

    float* pooled  = out + 2 * NROWS;
    float* fpooled = out + 2 * NROWS + NROWS * 90;

    reset_flags<<<1, 128>>>();
    mega<<<4509, 384, SMM>>>(frames, pooled, spp_w, spp_b, fw, fb,
                             b1i, b1h, w1i, w1h, w2i, w2h, b2i, b2h,
                             fc7_w, fc7_b, fc8w, fc8b, out, fpooled);
}

// round 17
// speedup vs baseline: 1.1780x; 1.0176x over previous
#include <cuda_runtime.h>
#include <cuda_bf16.h>
#include <math.h>

#define NROWS 2048
#define EMBED 4096
#define SPLITS 16

typedef unsigned long long ull;

__device__ __forceinline__ void ffma2(ull& d, ull a, ull b) {
    asm("fma.rn.f32x2 %0, %1, %2, %3;" : "=l"(d) : "l"(a), "l"(b), "l"(d));
}
__device__ __forceinline__ ull pack2f(float x, float y) {
    ull r; asm("mov.b64 %0, {%1, %2};" : "=l"(r) : "f"(x), "f"(y)); return r;
}
__device__ __forceinline__ float2 unpack2f(ull v) {
    float2 f; asm("mov.b64 {%0, %1}, %2;" : "=f"(f.x), "=f"(f.y) : "l"(v)); return f;
}
__device__ __forceinline__ int ld_acq(const int* p) {
    int v; asm volatile("ld.acquire.gpu.global.b32 %0, [%1];" : "=r"(v) : "l"(p)); return v;
}
__device__ __forceinline__ void st_rel(int* p, int v) {
    asm volatile("st.release.gpu.global.b32 [%0], %1;" :: "l"(p), "r"(v));
}

// ---------------- scratch ----------------
__device__ float g_part[SPLITS * NROWS * 64];
__device__ float g_XP[NROWS * 256];
__device__ float g_states[NROWS * 192];
__device__ float g_G[EMBED * 32];
__device__ float g_cvec[EMBED];
__device__ float g_b1c[256];
__device__ float g_b2c[128];
__device__ ull g_w1hP[32 * 256];
__device__ ull g_w2P[48 * 128];
__device__ ull g_wc1P[64 * 256];
__device__ float g_wc2Pf[96 * 128];
// flags
__device__ int g_prog[8];
__device__ int g_doneSPP[16];
__device__ int g_done90[16];
__device__ int g_doneRX[128];
__device__ int g_done32[16];
__device__ int g_doneRG[128];
__device__ int g_donePrep;

__device__ __forceinline__ float sig_f(float x) {
    return __fdividef(1.0f, 1.0f + __expf(-x));
}
__device__ __forceinline__ float tanh_f(float x) {
    return __fdividef(2.0f, 1.0f + __expf(-2.0f * x)) - 1.0f;
}

// ---------------- flag reset (replay-safe) ----------------
__global__ void reset_flags() {
    const int tid = threadIdx.x;
    if (tid < 8) g_prog[tid] = 0;
    if (tid < 16) { g_doneSPP[tid] = 0; g_done90[tid] = 0; g_done32[tid] = 0; }
    if (tid < 128) { g_doneRX[tid] = 0; g_doneRG[tid] = 0; }
    if (tid == 0) g_donePrep = 0;
}

// ---------------- shared mlp body ----------------
template<int KA, int KAP>
__device__ __forceinline__ void mlp_body(
        float* sm, int tid, int tile, int s,
        const float* __restrict__ Asrc, int lda, int aoff,
        const float* __restrict__ W1, const float* __restrict__ b1,
        const float* __restrict__ fc7) {
    constexpr int WS = KAP;
    constexpr int NW = (32 * KA + 255) / 256;
    float* A2 = sm;
    float* W2 = A2 + 128 * KAP;
    float* F2 = W2 + 32 * WS;
    float* Es = F2 + 64 * 36;
    const int m0 = tile * 128;
    for (int idx = tid; idx < 128 * KA; idx += 384) {
        int rr = idx / KA, p = idx - rr * KA;
        A2[rr * KAP + p] = __ldcg(&Asrc[(size_t)(m0 + rr) * lda + aoff + p]);
    }
    ull acc2[8][4];
#pragma unroll
    for (int i = 0; i < 8; i++)
#pragma unroll
        for (int j = 0; j < 4; j++) acc2[i][j] = 0ull;
    const int kbase = s * 256;
    const int txE = tid & 7, tyE = tid >> 3;
    const int txM = tid & 15, tyM = tid >> 4;
    const int eswM = 4 * (tyM & 7);
    const int fswM = 4 * (txM & 7);
    float pw[NW], pf[8];
    if (tid < 256) {
#pragma unroll
        for (int i = 0; i < NW; i++) {
            int idx = tid + i * 256;
            if (idx < 32 * KA) pw[i] = W1[(size_t)(kbase + idx / KA) * KA + idx % KA];
        }
#pragma unroll
        for (int i = 0; i < 8; i++) {
            int idx = tid + i * 256;
            pf[i] = fc7[(size_t)(idx >> 5) * 4096 + kbase + (idx & 31)];
        }
    }
    for (int kc = 0; kc < 256; kc += 32) {
        const int cg0 = kbase + kc;
        __syncthreads();
        if (tid < 256) {
#pragma unroll
            for (int i = 0; i < NW; i++) {
                int idx = tid + i * 256;
                if (idx < 32 * KA) W2[(idx / KA) * WS + idx % KA] = pw[i];
            }
#pragma unroll
            for (int i = 0; i < 8; i++) {
                int idx = tid + i * 256;
                int n = idx >> 5, kk = idx & 31;
                F2[n * 36 + (kk ^ (4 * ((n >> 2) & 7)))] = pf[i];
            }
        }
        __syncthreads();
        if (tid < 256) {
            if (kc + 32 < 256) {
                const int ng0 = cg0 + 32;
#pragma unroll
                for (int i = 0; i < NW; i++) {
                    int idx = tid + i * 256;
                    if (idx < 32 * KA) pw[i] = W1[(size_t)(ng0 + idx / KA) * KA + idx % KA];
                }
#pragma unroll
                for (int i = 0; i < 8; i++) {
                    int idx = tid + i * 256;
                    pf[i] = fc7[(size_t)(idx >> 5) * 4096 + ng0 + (idx & 31)];
                }
            }
            ull e2[4][4];
#pragma unroll
            for (int i = 0; i < 4; i++)
#pragma unroll
                for (int j = 0; j < 4; j++) e2[i][j] = 0ull;
#pragma unroll 15
            for (int p = 0; p < KA; p += 2) {
                ull a0 = *(const ull*)&A2[(tyE * 4 + 0) * KAP + p];
                ull a1 = *(const ull*)&A2[(tyE * 4 + 1) * KAP + p];
                ull a2 = *(const ull*)&A2[(tyE * 4 + 2) * KAP + p];
                ull a3 = *(const ull*)&A2[(tyE * 4 + 3) * KAP + p];
                ull w0 = *(const ull*)&W2[(txE * 4 + 0) * WS + p];
                ull w1 = *(const ull*)&W2[(txE * 4 + 1) * WS + p];
                ull w2 = *(const ull*)&W2[(txE * 4 + 2) * WS + p];
                ull w3 = *(const ull*)&W2[(txE * 4 + 3) * WS + p];
                ffma2(e2[0][0], a0, w0); ffma2(e2[0][1], a0, w1);
                ffma2(e2[0][2], a0, w2); ffma2(e2[0][3], a0, w3);
                ffma2(e2[1][0], a1, w0); ffma2(e2[1][1], a1, w1);
                ffma2(e2[1][2], a1, w2); ffma2(e2[1][3], a1, w3);
                ffma2(e2[2][0], a2, w0); ffma2(e2[2][1], a2, w1);
                ffma2(e2[2][2], a2, w2); ffma2(e2[2][3], a2, w3);
                ffma2(e2[3][0], a3, w0); ffma2(e2[3][1], a3, w1);
                ffma2(e2[3][2], a3, w2); ffma2(e2[3][3], a3, w3);
            }
#pragma unroll
            for (int i = 0; i < 4; i++) {
                int rr = tyE * 4 + i;
                int swz = 4 * ((rr >> 3) & 7);
#pragma unroll
                for (int j = 0; j < 4; j++) {
                    int c = txE * 4 + j;
                    float2 f = unpack2f(e2[i][j]);
                    float v = f.x + f.y + b1[cg0 + c];
                    Es[rr * 40 + (c ^ swz)] = fmaxf(v, 0.f);
                }
            }
        }
        __syncthreads();
        if (tid < 256) {
#pragma unroll
            for (int kk = 0; kk < 32; kk += 2) {
                ull e[8], fv[4];
#pragma unroll
                for (int i = 0; i < 8; i++)
                    e[i] = *(const ull*)&Es[(tyM * 8 + i) * 40 + (kk ^ eswM)];
#pragma unroll
                for (int j = 0; j < 4; j++)
                    fv[j] = *(const ull*)&F2[(txM * 4 + j) * 36 + (kk ^ fswM)];
#pragma unroll
                for (int i = 0; i < 8; i++)
#pragma unroll
                    for (int j = 0; j < 4; j++) ffma2(acc2[i][j], e[i], fv[j]);
            }
        }
    }
    if (tid < 256) {
#pragma unroll
        for (int i = 0; i < 8; i++)
#pragma unroll
            for (int j = 0; j < 4; j++) {
                float2 f = unpack2f(acc2[i][j]);
                g_part[((size_t)s * NROWS + m0 + tyM * 8 + i) * 64 + txM * 4 + j] = f.x + f.y;
            }
    }
    __threadfence();
    __syncthreads();
}

// rx (reduce_xp) body shared
__device__ __forceinline__ void rx_body(float* sm, int tid, int c,
                                        const float* __restrict__ fc7_b) {
    const int tile = c >> 3;
    const int r0 = c * 16;
    while (ld_acq(&g_done90[tile]) < 16) __nanosleep(256);
    float* embS = sm;   // [16][66]
    if (tid < 256) {
        int r = tid >> 4, ng = tid & 15;
        float4 acc = *(const float4*)&fc7_b[ng * 4];
#pragma unroll
        for (int ss = 0; ss < SPLITS; ss++) {
            float4 v = __ldcg((const float4*)&g_part[((size_t)ss * NROWS + r0 + r) * 64 + ng * 4]);
            acc.x += v.x; acc.y += v.y; acc.z += v.z; acc.w += v.w;
        }
        embS[r * 66 + ng * 4 + 0] = fmaxf(acc.x, 0.f);
        embS[r * 66 + ng * 4 + 1] = fmaxf(acc.y, 0.f);
        embS[r * 66 + ng * 4 + 2] = fmaxf(acc.z, 0.f);
        embS[r * 66 + ng * 4 + 3] = fmaxf(acc.w, 0.f);
    }
    __syncthreads();
    if (tid < 256) {
        ull w[32];
#pragma unroll
        for (int k = 0; k < 32; k++) w[k] = g_wc1P[k * 256 + tid];
        const float bias = g_b1c[tid];
        for (int r = 0; r < 16; r += 2) {
            ull a0 = pack2f(bias, 0.f), a1 = 0ull;
            ull c0 = pack2f(bias, 0.f), c1 = 0ull;
#pragma unroll
            for (int k = 0; k < 16; k++) {
                ffma2(a0, w[2 * k],     *(const ull*)&embS[r * 66 + 4 * k]);
                ffma2(a1, w[2 * k + 1], *(const ull*)&embS[r * 66 + 4 * k + 2]);
                ffma2(c0, w[2 * k],     *(const ull*)&embS[(r + 1) * 66 + 4 * k]);
                ffma2(c1, w[2 * k + 1], *(const ull*)&embS[(r + 1) * 66 + 4 * k + 2]);
            }
            float2 f0 = unpack2f(a0), f1 = unpack2f(a1);
            float2 g0 = unpack2f(c0), g1 = unpack2f(c1);
            g_XP[(size_t)(r0 + r) * 256 + tid]     = (f0.x + f0.y) + (f1.x + f1.y);
            g_XP[(size_t)(r0 + r + 1) * 256 + tid] = (g0.x + g0.y) + (g1.x + g1.y);
        }
    }
    __threadfence();
    __syncthreads();
    if (tid == 0) st_rel(&g_doneRX[c], 1);
}

// ================= MEGA layout =================
// 0-7 scan | 8-540 prep | 541-1308 spp even | 1309-1436 mlp90 even | 1437-1500 rx even |
// 1501-2268 spp odd | 2269-2396 mlp90 odd | 2397-2460 rx odd |
// 2461-2716 mlp32 | 2717-2844 RG | 2845-2972 tail
__global__ void __launch_bounds__(384, 1) mega(
        const float* __restrict__ frames, float* __restrict__ pooled,
        const float* __restrict__ spp_w, const float* __restrict__ spp_b,
        const float* __restrict__ fw, const float* __restrict__ fb,
        const float* __restrict__ b1i, const float* __restrict__ b1h,
        const float* __restrict__ w1i, const float* __restrict__ w1h,
        const float* __restrict__ w2i, const float* __restrict__ w2h,
        const float* __restrict__ b2i, const float* __restrict__ b2h,
        const float* __restrict__ fc7, const float* __restrict__ fc7_b,
        const float* __restrict__ fc8w, const float* __restrict__ fc8b,
        float* __restrict__ out, float* __restrict__ fpooled) {
    extern __shared__ float sm[];
    const int blk = blockIdx.x;
    const int tid = threadIdx.x;

    if (blk < 8) {
        // ---------------- scan role, resident from t=0, spins on flags ----------------
        while (ld_acq(&g_donePrep) < 533) __nanosleep(256);
        __shared__ __align__(16) float h1s[2][64];
        __shared__ __align__(16) float h2s[2][32];
        const int wid = tid >> 5, lane = tid & 31;
        const int b = blk;
        const float* xp = g_XP + (size_t)b * 65536;
        float* st = g_states + (size_t)b * 49152;
        ull wreg[48];
        float bc2 = 0.f, cst = 0.f;
        const int q = lane & 3;
        int j, r;
        if (wid < 8) {
            j = (wid << 3) + (lane >> 2);
            r = (q << 6) + j;
#pragma unroll
            for (int k = 0; k < 32; k++) wreg[k] = g_w1hP[k * 256 + r];
        } else {
            j = ((wid - 8) << 3) + (lane >> 2);
            r = (q << 5) + j;
#pragma unroll
            for (int k = 0; k < 48; k++) wreg[k] = g_w2P[k * 128 + r];
            bc2 = g_b2c[r];
        }
        if (tid < 64) { h1s[0][tid] = 0.f; h1s[1][tid] = 0.f; }
        if (tid >= 64 && tid < 96) { h2s[0][tid - 64] = 0.f; h2s[1][tid - 64] = 0.f; }
        while (ld_acq(&g_doneRX[16 * b]) < 1) __nanosleep(256);
        float xcur = 0.f, x1 = 0.f;
        if (wid < 8) { xcur = __ldcg(&xp[r]); x1 = __ldcg(&xp[256 + r]); }
        __syncthreads();
        for (int t = 0; t <= 256; t++) {
            if ((t & 31) == 0 && t) {
                __threadfence();
                __syncthreads();
                if (tid == 0) st_rel(&g_prog[b], t - 1);
            }
            const int buf = t & 1;
            if (wid < 8) {
                if (t < 256) {
                    float x2 = 0.f;
                    const int row2 = t + 2;
                    if (row2 < 256) {
                        if ((row2 & 15) == 0) {
                            while (ld_acq(&g_doneRX[16 * b + (row2 >> 4)]) < 1) __nanosleep(128);
                        }
                        x2 = __ldcg(&xp[row2 * 256 + r]);
                    }
                    const float* hb = h1s[buf];
                    ull a0 = pack2f(xcur, 0.f), a1 = 0ull, a2 = 0ull, a3 = 0ull;
#pragma unroll
                    for (int k = 0; k < 8; k++) {
                        ulonglong2 hA = *(const ulonglong2*)&hb[8 * k + 0];
                        ulonglong2 hB = *(const ulonglong2*)&hb[8 * k + 4];
                        ffma2(a0, wreg[4 * k + 0], hA.x);
                        ffma2(a1, wreg[4 * k + 1], hA.y);
                        ffma2(a2, wreg[4 * k + 2], hB.x);
                        ffma2(a3, wreg[4 * k + 3], hB.y);
                    }
                    float2 f0 = unpack2f(a0), f1 = unpack2f(a1);
                    float2 f2 = unpack2f(a2), f3 = unpack2f(a3);
                    float g = ((f0.x + f0.y) + (f1.x + f1.y)) + ((f2.x + f2.y) + (f3.x + f3.y));
                    float act = (q == 2) ? tanh_f(g) : sig_f(g);
                    const int base = lane & ~3;
                    float fi = __shfl_sync(0xffffffffu, act, base + 0);
                    float ff = __shfl_sync(0xffffffffu, act, base + 1);
                    float fg = __shfl_sync(0xffffffffu, act, base + 2);
                    float fo = __shfl_sync(0xffffffffu, act, base + 3);
                    if (q == 0) {
                        float c = ff * cst + fi * fg;
                        float h = fo * tanh_f(c);
                        cst = c;
                        h1s[buf ^ 1][j] = h;
                        st[t * 192 + j] = h;
                        st[t * 192 + 64 + j] = c;
                    }
                    xcur = x1; x1 = x2;
                }
            } else if (t >= 1) {
                const int tp = t - 1;
                const float* hb1 = h1s[buf];
                const float* hb2 = h2s[buf];
                ull a0 = pack2f(bc2, 0.f), a1 = 0ull, a2 = 0ull, a3 = 0ull;
#pragma unroll
                for (int k = 0; k < 8; k++) {
                    ulonglong2 hA = *(const ulonglong2*)&hb1[8 * k + 0];
                    ulonglong2 hB = *(const ulonglong2*)&hb1[8 * k + 4];
                    ffma2(a0, wreg[4 * k + 0], hA.x);
                    ffma2(a1, wreg[4 * k + 1], hA.y);
                    ffma2(a2, wreg[4 * k + 2], hB.x);
                    ffma2(a3, wreg[4 * k + 3], hB.y);
                }
#pragma unroll
                for (int k = 0; k < 4; k++) {
                    ulonglong2 hA = *(const ulonglong2*)&hb2[8 * k + 0];
                    ulonglong2 hB = *(const ulonglong2*)&hb2[8 * k + 4];
                    ffma2(a0, wreg[32 + 4 * k + 0], hA.x);
                    ffma2(a1, wreg[32 + 4 * k + 1], hA.y);
                    ffma2(a2, wreg[32 + 4 * k + 2], hB.x);
                    ffma2(a3, wreg[32 + 4 * k + 3], hB.y);
                }
                float2 f0 = unpack2f(a0), f1 = unpack2f(a1);
                float2 f2 = unpack2f(a2), f3 = unpack2f(a3);
                float g = ((f0.x + f0.y) + (f1.x + f1.y)) + ((f2.x + f2.y) + (f3.x + f3.y));
                float act = (q == 2) ? tanh_f(g) : sig_f(g);
                const int base = lane & ~3;
                float fi = __shfl_sync(0xffffffffu, act, base + 0);
                float ff = __shfl_sync(0xffffffffu, act, base + 1);
                float fg = __shfl_sync(0xffffffffu, act, base + 2);
                float fo = __shfl_sync(0xffffffffu, act, base + 3);
                if (q == 0) {
                    float c = ff * cst + fi * fg;
                    float h = fo * tanh_f(c);
                    cst = c;
                    h2s[buf ^ 1][j] = h;
                    st[tp * 192 + 128 + j] = h;
                    st[tp * 192 + 160 + j] = c;
                }
            }
            __syncthreads();
        }
        __threadfence();
        __syncthreads();
        if (tid == 0) st_rel(&g_prog[b], 256);
        return;
    }

    if (blk < 541) {
        // ---------------- prep roles ----------------
        const int pb = blk - 8;
        if (pb < 512) {
            if (tid < 256) {
                int o = pb * 256 + tid;
                int i = o >> 5, j = o & 31;
                float s = 0.f;
                for (int p = 0; p < 90; p++) s += spp_w[i * 90 + p] * fw[p * 32 + j];
                g_G[o] = s;
            }
        } else if (pb < 528) {
            if (tid < 256) {
                int i = (pb - 512) * 256 + tid;
                float s = spp_b[i];
                for (int p = 0; p < 90; p++) s += spp_w[i * 90 + p] * fb[p];
                g_cvec[i] = s;
            }
        } else if (pb == 528) {
            if (tid < 256) g_b1c[tid] = b1i[tid] + b1h[tid];
            if (tid < 128) g_b2c[tid] = b2i[tid] + b2h[tid];
        } else if (pb == 529) {
            for (int idx = tid; idx < 8192; idx += 384) {
                int k = idx >> 8, r = idx & 255;
                g_w1hP[idx] = pack2f(w1h[r * 64 + 2 * k], w1h[r * 64 + 2 * k + 1]);
            }
        } else if (pb == 530) {
            for (int idx = tid; idx < 6144; idx += 384) {
                int k = idx >> 7, r = idx & 127;
                ull v;
                if (k < 32) v = pack2f(w2i[r * 64 + 2 * k], w2i[r * 64 + 2 * k + 1]);
                else { int k2 = k - 32; v = pack2f(w2h[r * 32 + 2 * k2], w2h[r * 32 + 2 * k2 + 1]); }
                g_w2P[idx] = v;
            }
        } else if (pb == 531) {
            for (int idx = tid; idx < 16384; idx += 384) {
                int k = idx >> 8, r = idx & 255;
                ull v;
                if (k < 32) v = pack2f(w1i[r * 64 + 2 * k], w1i[r * 64 + 2 * k + 1]);
                else { int k2 = k - 32; v = pack2f(w1h[r * 64 + 2 * k2], w1h[r * 64 + 2 * k2 + 1]); }
                g_wc1P[idx] = v;
            }
        } else {
            for (int idx = tid; idx < 12288; idx += 384) {
                int k = idx >> 7, g = idx & 127;
                g_wc2Pf[idx] = (k < 64) ? w2i[g * 64 + k] : w2h[g * 32 + (k - 64)];
            }
        }
        __threadfence();
        __syncthreads();
        if (tid == 0) atomicAdd(&g_donePrep, 1);
        return;
    }

    if ((blk >= 541 && blk < 1309) || (blk >= 1501 && blk < 2269)) {
        // ---------------- SPP role: 4 image-channels per block (2 rounds of 2) ----------------
        __shared__ float tmax2[2][144];
        const bool even = (blk < 1309);
        const int p = even ? (blk - 541) : (blk - 1501);
        const int tileIdx = p / 96;
        const int tile = even ? 2 * tileIdx : 2 * tileIdx + 1;
        const int within = p - tileIdx * 96;
        const int nc0 = tile * 384 + 4 * within;
        const int grp = tid / 192, lt = tid - grp * 192;
        for (int rnd = 0; rnd < 2; rnd++) {
            const int nc = nc0 + 2 * rnd + grp;
            if (rnd) __syncthreads();
            if (lt < 144) {
                const float* img = frames + (size_t)nc * 9216;
                const int ti = lt / 12, tj = lt % 12;
                const float* pp = img + ti * 8 * 96 + tj * 8;
                float m = -3.402823466e38f;
#pragma unroll
                for (int r = 0; r < 8; r++) {
                    float4 v0 = *(const float4*)(pp + r * 96);
                    float4 v1 = *(const float4*)(pp + r * 96 + 4);
                    m = fmaxf(m, fmaxf(fmaxf(v0.x, v0.y), fmaxf(v0.z, v0.w)));
                    m = fmaxf(m, fmaxf(fmaxf(v1.x, v1.y), fmaxf(v1.z, v1.w)));
                }
                tmax2[grp][lt] = m;
            }
            __syncthreads();
            const float* tmax = tmax2[grp];
            const int n = nc / 3, c = nc - 3 * n;
            float* orow = pooled + (size_t)n * 90;
            if (lt < 16) {
                int i = lt / 4, j = lt % 4;
                float m = -3.402823466e38f;
                for (int a = 0; a < 3; a++) for (int b = 0; b < 3; b++)
                    m = fmaxf(m, tmax[(i * 3 + a) * 12 + (j * 3 + b)]);
                orow[c * 16 + i * 4 + j] = m;
            } else if (lt < 25) {
                int q = lt - 16, i = q / 3, j = q % 3;
                float m = -3.402823466e38f;
                for (int a = 0; a < 4; a++) for (int b = 0; b < 4; b++)
                    m = fmaxf(m, tmax[(i * 4 + a) * 12 + (j * 4 + b)]);
                orow[48 + c * 9 + i * 3 + j] = m;
            } else if (lt < 29) {
                int q = lt - 25, i = q / 2, j = q % 2;
                float m = -3.402823466e38f;
                for (int a = 0; a < 6; a++) for (int b = 0; b < 6; b++)
                    m = fmaxf(m, tmax[(i * 6 + a) * 12 + (j * 6 + b)]);
                orow[75 + c * 4 + i * 2 + j] = m;
            } else if (lt == 29) {
                float m = -3.402823466e38f;
                for (int a = 0; a < 144; a++) m = fmaxf(m, tmax[a]);
                orow[87 + c] = m;
            }
        }
        __threadfence();
        __syncthreads();
        if (tid == 0) atomicAdd(&g_doneSPP[tile], 1);
        return;
    }

    if ((blk >= 1309 && blk < 1437) || (blk >= 2269 && blk < 2397)) {
        // ---------------- mlp90 role ----------------
        while (ld_acq(&g_donePrep) < 533) __nanosleep(256);
        const int idx0 = (blk < 1437) ? (blk - 1309) : (blk - 2269);
        const int tile = (blk < 1437) ? 2 * (idx0 >> 4) : 2 * (idx0 >> 4) + 1;
        const int s = idx0 & 15;
        while (ld_acq(&g_doneSPP[tile]) < 96) __nanosleep(256);
        mlp_body<90, 90>(sm, tid, tile, s, pooled, 90, 0, spp_w, spp_b, fc7);
        if (tid == 0) atomicAdd(&g_done90[tile], 1);
        return;
    }

    if ((blk >= 1437 && blk < 1501) || (blk >= 2397 && blk < 2461)) {
        // ---------------- reduce_xp role; k outer, batch inner ----------------
        while (ld_acq(&g_donePrep) < 533) __nanosleep(256);
        const int idx0 = (blk < 1501) ? (blk - 1437) : (blk - 2397);
        const int k = idx0 >> 3, b = idx0 & 7;
        const int c = 16 * b + ((blk < 1501) ? k : (8 + k));
        rx_body(sm, tid, c, fc7_b);
        return;
    }

    if (blk >= 2461 && blk < 2717) {
        // ---------------- mlp32 role ----------------
        while (ld_acq(&g_donePrep) < 533) __nanosleep(256);
        const int m = blk - 2461;
        const int u = m >> 4;
        const int tile = (u < 8) ? (2 * u) : (2 * (u - 8) + 1);
        const int s = m & 15;
        const int m0 = tile * 128;
        const int b = m0 >> 8;
        const int needed = (m0 & 255) + 128;
        while (ld_acq(&g_prog[b]) < needed) __nanosleep(256);
        mlp_body<32, 34>(sm, tid, tile, s, g_states, 192, 128, g_G, g_cvec, fc7);
        if (tid == 0) atomicAdd(&g_done32[tile], 1);
        return;
    }

    if (blk >= 2717 && blk < 2845) {
        // ---------------- reduce_gates role ----------------
        while (ld_acq(&g_donePrep) < 533) __nanosleep(256);
        float* S = sm;   // [16][132]
        const int c = blk - 2717;
        const int r0 = c * 16;
        const int tile = c >> 3;
        while (ld_acq(&g_done32[tile]) < 16) __nanosleep(256);
        if (tid < 256) {
            int r = tid >> 4, ng = tid & 15;
            float4 acc = *(const float4*)&fc7_b[ng * 4];
#pragma unroll
            for (int ss = 0; ss < SPLITS; ss++) {
                float4 v = __ldcg((const float4*)&g_part[((size_t)ss * NROWS + r0 + r) * 64 + ng * 4]);
                acc.x += v.x; acc.y += v.y; acc.z += v.z; acc.w += v.w;
            }
            S[r * 132 + ng * 4 + 0] = fmaxf(acc.x, 0.f);
            S[r * 132 + ng * 4 + 1] = fmaxf(acc.y, 0.f);
            S[r * 132 + ng * 4 + 2] = fmaxf(acc.z, 0.f);
            S[r * 132 + ng * 4 + 3] = fmaxf(acc.w, 0.f);
            float4 h = __ldcg((const float4*)&g_states[(size_t)(r0 + r) * 192 + ng * 4]);
            *(float4*)&S[r * 132 + 64 + ng * 4] = h;
        }
        __syncthreads();
        if (tid < 256) {
            ull wc[64];
#pragma unroll
            for (int k = 0; k < 64; k++) wc[k] = g_wc1P[k * 256 + tid];
            const float bias = g_b1c[tid];
            for (int r = 0; r < 16; r += 2) {
                ull a0 = pack2f(bias, 0.f), a1 = 0ull;
                ull c0 = pack2f(bias, 0.f), c1 = 0ull;
#pragma unroll
                for (int k = 0; k < 32; k++) {
                    ffma2(a0, wc[2 * k],     *(const ull*)&S[r * 132 + 4 * k]);
                    ffma2(a1, wc[2 * k + 1], *(const ull*)&S[r * 132 + 4 * k + 2]);
                    ffma2(c0, wc[2 * k],     *(const ull*)&S[(r + 1) * 132 + 4 * k]);
                    ffma2(c1, wc[2 * k + 1], *(const ull*)&S[(r + 1) * 132 + 4 * k + 2]);
                }
                float2 f0 = unpack2f(a0), f1 = unpack2f(a1);
                float2 g0 = unpack2f(c0), g1 = unpack2f(c1);
                g_XP[(size_t)(r0 + r) * 256 + tid]     = (f0.x + f0.y) + (f1.x + f1.y);
                g_XP[(size_t)(r0 + r + 1) * 256 + tid] = (g0.x + g0.y) + (g1.x + g1.y);
            }
        }
        __threadfence();
        __syncthreads();
        if (tid == 0) st_rel(&g_doneRG[c], 1);
        return;
    }

    // ---------------- tail role ----------------
    {
        while (ld_acq(&g_donePrep) < 533) __nanosleep(256);
        float* fwS = sm;                  // [90][34]
        __shared__ float fh1[64], th2s[32], tc2s[32], gs[128];
        const int c = blk - 2845;
        const int r0 = c * 16;
        for (int idx = tid; idx < 2880; idx += 384)
            fwS[(idx >> 5) * 34 + (idx & 31)] = fw[idx];
        while (ld_acq(&g_doneRG[c]) < 1) __nanosleep(256);
        float wcat[96];
        float fwr[32];
        float b2 = 0.f, w8 = 0.f;
        const int po = tid - 32;
        if (tid < 128) {
#pragma unroll
            for (int k = 0; k < 96; k++) wcat[k] = g_wc2Pf[k * 128 + tid];
            b2 = g_b2c[tid];
            if (tid < 32) w8 = fc8w[tid];
        }
        __syncthreads();
        if (po >= 0 && po < 90) {
#pragma unroll
            for (int k = 0; k < 32; k++) fwr[k] = fwS[po * 34 + k];
        }
        const float b8 = fc8b[0];
        const bool is_tanh2 = (tid >= 64 && tid < 96);
        for (int r = 0; r < 16; r++) {
            const int row = r0 + r;
            const float* xpf = g_XP + (size_t)row * 256;
            const float* st = g_states + (size_t)row * 192;
            if (tid < 64) {
                float i = sig_f(__ldcg(&xpf[tid]));
                float f = sig_f(__ldcg(&xpf[64 + tid]));
                float gg = tanh_f(__ldcg(&xpf[128 + tid]));
                float o = sig_f(__ldcg(&xpf[192 + tid]));
                float cn = f * __ldcg(&st[64 + tid]) + i * gg;
                fh1[tid] = o * tanh_f(cn);
            } else if (tid < 96) {
                th2s[tid - 64] = __ldcg(&st[128 + (tid - 64)]);
            } else if (tid < 128) {
                tc2s[tid - 96] = __ldcg(&st[160 + (tid - 96)]);
            }
            __syncthreads();
            if (tid < 128) {
                float a = b2;
#pragma unroll
                for (int k = 0; k < 64; k++) a += wcat[k] * fh1[k];
#pragma unroll
                for (int k = 0; k < 32; k++) a += wcat[64 + k] * th2s[k];
                gs[tid] = is_tanh2 ? tanh_f(a) : sig_f(a);
            }
            __syncthreads();
            if (tid < 32) {
                float cn = gs[32 + tid] * tc2s[tid] + gs[tid] * gs[64 + tid];
                float fh2 = gs[96 + tid] * tanh_f(cn);
                float v1 = th2s[tid] * w8;
                float v2 = fh2 * w8;
#pragma unroll
                for (int off = 16; off > 0; off >>= 1) {
                    v1 += __shfl_down_sync(0xffffffffu, v1, off);
                    v2 += __shfl_down_sync(0xffffffffu, v2, off);
                }
                if (tid == 0) {
                    out[row] = sig_f(v1 + b8);
                    out[NROWS + row] = sig_f(v2 + b8);
                }
            } else if (po >= 0 && po < 90) {
                float s2 = fb[po];
#pragma unroll
                for (int k = 0; k < 32; k++) s2 += fwr[k] * th2s[k];
                fpooled[(size_t)row * 90 + po] = s2;
            }
            __syncthreads();
        }
    }
}

// ---------------- host ----------------
extern "C" void kernel_launch(void* const* d_in, const int* in_sizes, int n_in,
                              void* d_out, int out_size) {
    const float* frames = (const float*)d_in[0];
    const float* spp_w  = (const float*)d_in[1];
    const float* spp_b  = (const float*)d_in[2];
    const float* fc7_w  = (const float*)d_in[3];
    const float* fc7_b  = (const float*)d_in[4];
    const float* w1i    = (const float*)d_in[5];
    const float* w1h    = (const float*)d_in[6];
    const float* b1i    = (const float*)d_in[7];
    const float* b1h    = (const float*)d_in[8];
    const float* w2i    = (const float*)d_in[9];
    const float* w2h    = (const float*)d_in[10];
    const float* b2i    = (const float*)d_in[11];
    const float* b2h    = (const float*)d_in[12];
    const float* fw     = (const float*)d_in[13];
    const float* fb     = (const float*)d_in[14];
    const float* fc8w   = (const float*)d_in[15];
    const float* fc8b   = (const float*)d_in[16];
    float* out = (float*)d_out;

    const int SMM = (128 * 90 + 32 * 90 + 64 * 36 + 128 * 40) * 4;
    cudaFuncSetAttribute(mega, cudaFuncAttributeMaxDynamicSharedMemorySize, SMM);

    float* pooled  = out + 2 * NROWS;
    float* fpooled = out + 2 * NROWS + NROWS * 90;

    reset_flags<<<1, 128>>>();
    mega<<<2973, 384, SMM>>>(frames, pooled, spp_w, spp_b, fw, fb,
                             b1i, b1h, w1i, w1h, w2i, w2h, b2i, b2h,
                             fc7_w, fc7_b, fc8w, fc8b, out, fpooled);
}